// round 1
// baseline (speedup 1.0000x reference)
#include <cuda_runtime.h>
#include <math.h>

// ---------------------------------------------------------------------------
// Swin block: B=32, H=W=56, D=192, HEADS=6, DH=32, WS=7, SHIFT=3, no pad,
// and (per reference) NO attention mask despite the shift.
// ---------------------------------------------------------------------------

#define NB    32
#define NHW   3136            // 56*56
#define NTOK  100352          // 32*3136
#define DIM   192
#define NHEAD 6
#define DH    32
#define NWIN  2048            // 32 * 8 * 8
#define NPOS  49

// Scratch (device globals; no allocation allowed)
__device__ float g_buf1[(size_t)NTOK * DIM];   // xn (window order) -> attn o -> xn2
__device__ float g_buf2[(size_t)NTOK * 576];   // qkv -> mlp hidden (384)
__device__ float g_buf3[(size_t)NTOK * DIM];   // x2 (post-attention, plain order)

// window-order row r -> original-layout index (also equals the shifted-source
// index: roll(-3) gather and roll(+3) scatter use the same mapping).
__device__ __forceinline__ int src_index(int r) {
    int w = r / 49, p = r % 49;
    int b  = w >> 6;
    int wy = (w & 63) >> 3;
    int wx = w & 7;
    int py = p / 7, px = p % 7;
    int h2 = wy * 7 + py;
    int w2 = wx * 7 + px;
    int hs = h2 + 3; if (hs >= 56) hs -= 56;
    int ws = w2 + 3; if (ws >= 56) ws -= 56;
    return b * NHW + hs * 56 + ws;
}

// ---------------------------------------------------------------------------
// LayerNorm kernel: one warp per token (192 = 6 floats/lane).
// GATHER=true: read via shifted/window mapping (LN1); else plain rows (LN2).
// ---------------------------------------------------------------------------
template <bool GATHER>
__global__ void ln_kernel(const float* __restrict__ x,
                          const float* __restrict__ gam,
                          const float* __restrict__ bet,
                          float* __restrict__ out) {
    int t    = blockIdx.x * 8 + (threadIdx.x >> 5);
    int lane = threadIdx.x & 31;
    int srow = GATHER ? src_index(t) : t;
    const float* xr = x + (size_t)srow * DIM;

    float v[6];
#pragma unroll
    for (int i = 0; i < 6; i++) v[i] = xr[lane + 32 * i];

    float s = v[0] + v[1] + v[2] + v[3] + v[4] + v[5];
#pragma unroll
    for (int o = 16; o; o >>= 1) s += __shfl_xor_sync(0xffffffffu, s, o);
    float mean = s * (1.0f / 192.0f);

    float q = 0.0f;
#pragma unroll
    for (int i = 0; i < 6; i++) { float d = v[i] - mean; q += d * d; }
#pragma unroll
    for (int o = 16; o; o >>= 1) q += __shfl_xor_sync(0xffffffffu, q, o);
    float rstd = rsqrtf(q * (1.0f / 192.0f) + 1e-5f);

    float* orow = out + (size_t)t * DIM;
#pragma unroll
    for (int i = 0; i < 6; i++) {
        int c = lane + 32 * i;
        orow[c] = (v[i] - mean) * rstd * gam[c] + bet[c];
    }
}

// ---------------------------------------------------------------------------
// Tiled fp32 GEMM: C[M,N] = A[M,K] * W[N,K]^T + bias, with epilogues.
//   EPI 0: store
//   EPI 1: exact-erf GELU then store
//   EPI 2: += res[row*N+col], store to out[row*N+col]         (N==192)
//   EPI 3: += res[src*192+col], store to out[src*192+col]     (N==192, scatter)
// BM=128, BN=64, BK=16, 256 threads, 8x4 micro-tile.
// Requires M%128==0, N%64==0, K%16==0 (true for all our shapes).
// ---------------------------------------------------------------------------
#define BM 128
#define BN 64
#define BK 16
#define LDA 132   // 128 + 4 pad (floats); 132*4 % 16 == 0
#define LDB 68    // 64 + 4 pad

__device__ __forceinline__ float gelu_exact(float v) {
    return 0.5f * v * (1.0f + erff(v * 0.7071067811865476f));
}

template <int EPI>
__global__ void gemm_kernel(const float* __restrict__ A,
                            const float* __restrict__ W,
                            const float* __restrict__ bias,
                            float* __restrict__ out,
                            const float* __restrict__ res,
                            int N, int K) {
    __shared__ float As[BK * LDA];
    __shared__ float Bs[BK * LDB];

    const int tid = threadIdx.x;
    const int tx = tid & 15;          // 16 col-groups of 4
    const int ty = tid >> 4;          // 16 row-groups of 8
    const int row0 = blockIdx.y * BM;
    const int col0 = blockIdx.x * BN;

    // A loads: 512 float4 per tile -> 2 per thread
    const int ar0 = (tid * 2 + 0) >> 2;          // rows 0..127
    const int ak0 = ((tid * 2 + 0) & 3) * 4;
    const int ar1 = (tid * 2 + 1) >> 2;
    const int ak1 = ((tid * 2 + 1) & 3) * 4;
    // B loads: 256 float4 per tile -> 1 per thread
    const int br = tid >> 2;                     // rows 0..63
    const int bk = (tid & 3) * 4;

    const float* Ag0 = A + (size_t)(row0 + ar0) * K + ak0;
    const float* Ag1 = A + (size_t)(row0 + ar1) * K + ak1;
    const float* Wg  = W + (size_t)(col0 + br) * K + bk;

    float acc[8][4];
#pragma unroll
    for (int i = 0; i < 8; i++)
#pragma unroll
        for (int j = 0; j < 4; j++) acc[i][j] = 0.0f;

    for (int k0 = 0; k0 < K; k0 += BK) {
        float4 a0 = *(const float4*)(Ag0 + k0);
        float4 a1 = *(const float4*)(Ag1 + k0);
        float4 wv = *(const float4*)(Wg + k0);
        As[(ak0 + 0) * LDA + ar0] = a0.x;
        As[(ak0 + 1) * LDA + ar0] = a0.y;
        As[(ak0 + 2) * LDA + ar0] = a0.z;
        As[(ak0 + 3) * LDA + ar0] = a0.w;
        As[(ak1 + 0) * LDA + ar1] = a1.x;
        As[(ak1 + 1) * LDA + ar1] = a1.y;
        As[(ak1 + 2) * LDA + ar1] = a1.z;
        As[(ak1 + 3) * LDA + ar1] = a1.w;
        Bs[(bk + 0) * LDB + br] = wv.x;
        Bs[(bk + 1) * LDB + br] = wv.y;
        Bs[(bk + 2) * LDB + br] = wv.z;
        Bs[(bk + 3) * LDB + br] = wv.w;
        __syncthreads();

#pragma unroll
        for (int kk = 0; kk < BK; kk++) {
            float4 fa0 = *(const float4*)&As[kk * LDA + ty * 8];
            float4 fa1 = *(const float4*)&As[kk * LDA + ty * 8 + 4];
            float4 fb  = *(const float4*)&Bs[kk * LDB + tx * 4];
            float ar[8] = {fa0.x, fa0.y, fa0.z, fa0.w, fa1.x, fa1.y, fa1.z, fa1.w};
            float brr[4] = {fb.x, fb.y, fb.z, fb.w};
#pragma unroll
            for (int i = 0; i < 8; i++)
#pragma unroll
                for (int j = 0; j < 4; j++) acc[i][j] += ar[i] * brr[j];
        }
        __syncthreads();
    }

    const int colb = col0 + tx * 4;
    float4 bv = *(const float4*)&bias[colb];

#pragma unroll
    for (int i = 0; i < 8; i++) {
        int row = row0 + ty * 8 + i;
        float4 r;
        r.x = acc[i][0] + bv.x;
        r.y = acc[i][1] + bv.y;
        r.z = acc[i][2] + bv.z;
        r.w = acc[i][3] + bv.w;
        if (EPI == 1) {
            r.x = gelu_exact(r.x); r.y = gelu_exact(r.y);
            r.z = gelu_exact(r.z); r.w = gelu_exact(r.w);
            *(float4*)&out[(size_t)row * N + colb] = r;
        } else if (EPI == 2) {
            float4 rv = *(const float4*)&res[(size_t)row * 192 + colb];
            r.x += rv.x; r.y += rv.y; r.z += rv.z; r.w += rv.w;
            *(float4*)&out[(size_t)row * 192 + colb] = r;
        } else if (EPI == 3) {
            int d = src_index(row);
            float4 rv = *(const float4*)&res[(size_t)d * 192 + colb];
            r.x += rv.x; r.y += rv.y; r.z += rv.z; r.w += rv.w;
            *(float4*)&out[(size_t)d * 192 + colb] = r;
        } else {
            *(float4*)&out[(size_t)row * N + colb] = r;
        }
    }
}

// ---------------------------------------------------------------------------
// Attention: one block per window (2048). qkv window [49][576] in dyn smem
// (row stride 584 to dodge bank conflicts), one warp per head.
// ---------------------------------------------------------------------------
#define QS 584
#define SS 52
#define ATTN_SMEM ((49 * QS + 6 * 49 * SS) * 4)   // 175,616 B

__global__ void attn_kernel(const float* __restrict__ qkv, float* __restrict__ o) {
    extern __shared__ float sm[];
    float* qk = sm;                 // 49 * 584
    float* sc = sm + 49 * QS;       // 6 * 49 * 52

    const int w = blockIdx.x;
    const float* src = qkv + (size_t)w * (49 * 576);

    for (int idx = threadIdx.x; idx < 49 * 144; idx += blockDim.x) {
        int r = idx / 144, c = idx % 144;
        float4 v = *(const float4*)(src + r * 576 + c * 4);
        *(float4*)&qk[r * QS + c * 4] = v;
    }
    __syncthreads();

    const int warp = threadIdx.x >> 5;
    const int lane = threadIdx.x & 31;
    if (warp >= 6) return;
    const int h = warp;
    float* S = sc + h * 49 * SS;
    const float scale = 0.17677669529663687f;  // 1/sqrt(32)

    // S = scale * Q Kt  (lane owns column j)
#pragma unroll
    for (int jp = 0; jp < 2; jp++) {
        int j = jp * 32 + lane;
        if (j < 49) {
            float4 kr[8];
            const float* kb = qk + j * QS + 192 + h * 32;
#pragma unroll
            for (int t = 0; t < 8; t++) kr[t] = *(const float4*)(kb + t * 4);
            for (int i = 0; i < 49; i++) {
                const float* qb = qk + i * QS + h * 32;
                float s = 0.0f;
#pragma unroll
                for (int t = 0; t < 8; t++) {
                    float4 q4 = *(const float4*)(qb + t * 4);
                    s += q4.x * kr[t].x + q4.y * kr[t].y + q4.z * kr[t].z + q4.w * kr[t].w;
                }
                S[i * SS + j] = s * scale;
            }
        }
    }
    __syncwarp();

    // softmax (lane owns row r)
#pragma unroll
    for (int rp = 0; rp < 2; rp++) {
        int r = rp * 32 + lane;
        if (r < 49) {
            float* Sr = S + r * SS;
            float mx = Sr[0];
            for (int j = 1; j < 49; j++) mx = fmaxf(mx, Sr[j]);
            float sum = 0.0f;
            for (int j = 0; j < 49; j++) { float e = expf(Sr[j] - mx); Sr[j] = e; sum += e; }
            float inv = 1.0f / sum;
            for (int j = 0; j < 49; j++) Sr[j] *= inv;
        }
    }
    __syncwarp();

    // O = P V  (lane owns head-dim d)
    float vr[49];
    const float* vb = qk + 384 + h * 32 + lane;
#pragma unroll
    for (int j = 0; j < 49; j++) vr[j] = vb[j * QS];

    float* ob = o + (size_t)w * (49 * 192) + h * 32 + lane;
    for (int i = 0; i < 49; i++) {
        const float* Si = S + i * SS;
        float a = 0.0f;
#pragma unroll 7
        for (int j = 0; j < 49; j++) a += Si[j] * vr[j];
        ob[i * 192] = a;
    }
}

// ---------------------------------------------------------------------------
// Launcher
// ---------------------------------------------------------------------------
extern "C" void kernel_launch(void* const* d_in, const int* in_sizes, int n_in,
                              void* d_out, int out_size) {
    const float* x     = (const float*)d_in[0];
    const float* ln1_g = (const float*)d_in[1];
    const float* ln1_b = (const float*)d_in[2];
    const float* ln2_g = (const float*)d_in[3];
    const float* ln2_b = (const float*)d_in[4];
    const float* w_qkv = (const float*)d_in[5];
    const float* b_qkv = (const float*)d_in[6];
    const float* w_out = (const float*)d_in[7];
    const float* b_out = (const float*)d_in[8];
    const float* w1    = (const float*)d_in[9];
    const float* b1    = (const float*)d_in[10];
    const float* w2    = (const float*)d_in[11];
    const float* b2    = (const float*)d_in[12];
    float* out = (float*)d_out;

    float *buf1, *buf2, *buf3;
    cudaGetSymbolAddress((void**)&buf1, g_buf1);
    cudaGetSymbolAddress((void**)&buf2, g_buf2);
    cudaGetSymbolAddress((void**)&buf3, g_buf3);

    cudaFuncSetAttribute(attn_kernel,
                         cudaFuncAttributeMaxDynamicSharedMemorySize, ATTN_SMEM);

    const int MT = NTOK / BM;   // 784

    // 1) LN1 + shift + window partition -> buf1 (window order)
    ln_kernel<true><<<NTOK / 8, 256>>>(x, ln1_g, ln1_b, buf1);
    // 2) QKV GEMM -> buf2 [NTOK, 576]
    gemm_kernel<0><<<dim3(576 / BN, MT), 256>>>(buf1, w_qkv, b_qkv, buf2, nullptr, 576, 192);
    // 3) windowed attention -> buf1 [NTOK, 192] (window order)
    attn_kernel<<<NWIN, 256, ATTN_SMEM>>>(buf2, buf1);
    // 4) proj + residual + reverse/unshift scatter -> buf3 (plain order)
    gemm_kernel<3><<<dim3(192 / BN, MT), 256>>>(buf1, w_out, b_out, buf3, x, 192, 192);
    // 5) LN2 -> buf1 (plain order)
    ln_kernel<false><<<NTOK / 8, 256>>>(buf3, ln2_g, ln2_b, buf1);
    // 6) fc1 + GELU -> buf2 [NTOK, 384]
    gemm_kernel<1><<<dim3(384 / BN, MT), 256>>>(buf1, w1, b1, buf2, nullptr, 384, 192);
    // 7) fc2 + residual -> d_out
    gemm_kernel<2><<<dim3(192 / BN, MT), 256>>>(buf2, w2, b2, out, buf3, 192, 384);
}

// round 3
// speedup vs baseline: 1.4605x; 1.4605x over previous
#include <cuda_runtime.h>
#include <math.h>
#include <stdint.h>

// ---------------------------------------------------------------------------
// Swin block: B=32, H=W=56, D=192, HEADS=6, DH=32, WS=7, SHIFT=3, no pad,
// no attention mask (per reference). GEMMs on tf32 mma.sync (legacy HMMA path,
// since bench ptxas target is plain sm_100 -> tcgen05 unavailable).
// ---------------------------------------------------------------------------

#define NHW   3136
#define NTOK  100352          // 32*3136
#define DIM   192
#define NWIN  2048            // 32 * 8 * 8

__device__ float g_buf1[(size_t)NTOK * DIM];
__device__ float g_buf2[(size_t)NTOK * 576];
__device__ float g_buf3[(size_t)NTOK * DIM];

__device__ __forceinline__ int src_index(int r) {
    int w = r / 49, p = r % 49;
    int b  = w >> 6;
    int wy = (w & 63) >> 3;
    int wx = w & 7;
    int py = p / 7, px = p % 7;
    int h2 = wy * 7 + py;
    int w2 = wx * 7 + px;
    int hs = h2 + 3; if (hs >= 56) hs -= 56;
    int ws = w2 + 3; if (ws >= 56) ws -= 56;
    return b * NHW + hs * 56 + ws;
}

// ---------------------------------------------------------------------------
// PTX helpers (all sm_80+ features; safe on plain sm_100 target)
// ---------------------------------------------------------------------------
__device__ __forceinline__ uint32_t smem_u32(const void* p) {
    uint32_t a;
    asm("{ .reg .u64 t; cvta.to.shared.u64 t, %1; cvt.u32.u64 %0, t; }" : "=r"(a) : "l"(p));
    return a;
}
__device__ __forceinline__ void cp_async16(uint32_t dst, const void* src) {
    asm volatile("cp.async.ca.shared.global [%0], [%1], 16;" :: "r"(dst), "l"(src));
}
#define CP_COMMIT()  asm volatile("cp.async.commit_group;" ::: "memory")
#define CP_WAIT(n)   asm volatile("cp.async.wait_group %0;" :: "n"(n) : "memory")

__device__ __forceinline__ uint32_t to_tf32(float f) {
    uint32_t r;
    asm("cvt.rna.tf32.f32 %0, %1;" : "=r"(r) : "f"(f));
    return r;
}
__device__ __forceinline__ void mma_tf32(float* c, const uint32_t* a, const uint32_t* b) {
    asm volatile(
        "mma.sync.aligned.m16n8k8.row.col.f32.tf32.tf32.f32 "
        "{%0,%1,%2,%3}, {%4,%5,%6,%7}, {%8,%9}, {%0,%1,%2,%3};"
        : "+f"(c[0]), "+f"(c[1]), "+f"(c[2]), "+f"(c[3])
        : "r"(a[0]), "r"(a[1]), "r"(a[2]), "r"(a[3]), "r"(b[0]), "r"(b[1]));
}

__device__ __forceinline__ float gelu_exact(float v) {
    return 0.5f * v * (1.0f + erff(v * 0.7071067811865476f));
}

// ---------------------------------------------------------------------------
// LayerNorm: one warp per token.
// ---------------------------------------------------------------------------
template <bool GATHER>
__global__ void ln_kernel(const float* __restrict__ x,
                          const float* __restrict__ gam,
                          const float* __restrict__ bet,
                          float* __restrict__ out) {
    int t    = blockIdx.x * 8 + (threadIdx.x >> 5);
    int lane = threadIdx.x & 31;
    int srow = GATHER ? src_index(t) : t;
    const float* xr = x + (size_t)srow * DIM;

    float v[6];
#pragma unroll
    for (int i = 0; i < 6; i++) v[i] = xr[lane + 32 * i];

    float s = v[0] + v[1] + v[2] + v[3] + v[4] + v[5];
#pragma unroll
    for (int o = 16; o; o >>= 1) s += __shfl_xor_sync(0xffffffffu, s, o);
    float mean = s * (1.0f / 192.0f);

    float q = 0.0f;
#pragma unroll
    for (int i = 0; i < 6; i++) { float d = v[i] - mean; q += d * d; }
#pragma unroll
    for (int o = 16; o; o >>= 1) q += __shfl_xor_sync(0xffffffffu, q, o);
    float rstd = rsqrtf(q * (1.0f / 192.0f) + 1e-5f);

    float* orow = out + (size_t)t * DIM;
#pragma unroll
    for (int i = 0; i < 6; i++) {
        int c = lane + 32 * i;
        orow[c] = (v[i] - mean) * rstd * gam[c] + bet[c];
    }
}

// ---------------------------------------------------------------------------
// tf32 mma.sync GEMM: C[M,N] = A[M,K] @ W[N,K]^T + bias (+epilogue)
// BM=128, BN=64, BK=16; 8 warps, warp tile 32x32 (2x4 m16n8k8 frags).
// SMEM row stride 20 floats -> all 32 banks hit exactly once per LDS frag.
// cp.async double-buffered K pipeline.
//   EPI 0: store   EPI 1: exact-erf GELU
//   EPI 2: += res[row], store   EPI 3: += res[src_index(row)], scatter
// ---------------------------------------------------------------------------
#define BM 128
#define BN 64
#define BK 16
#define LDS_R 20   // BK + 4 pad, floats

template <int EPI>
__global__ __launch_bounds__(256, 2)
void mma_gemm(const float* __restrict__ A, const float* __restrict__ W,
              const float* __restrict__ bias, float* __restrict__ out,
              const float* __restrict__ res, int N, int K) {
    __shared__ float As[2][BM * LDS_R];
    __shared__ float Ws[2][BN * LDS_R];

    const int tid  = threadIdx.x;
    const int wid  = tid >> 5;
    const int lane = tid & 31;
    const int g    = lane >> 2;       // group id 0..7
    const int tin  = lane & 3;        // thread-in-group 0..3
    const int wm   = (wid & 3) * 32;  // warp m offset in tile
    const int wn   = (wid >> 2) * 32; // warp n offset in tile
    const int row0 = blockIdx.y * BM;
    const int col0 = blockIdx.x * BN;

    // global load assignments (16B chunks)
    const int ar0 = (tid * 2 + 0) >> 2, ac0 = ((tid * 2 + 0) & 3) * 4;
    const int ar1 = (tid * 2 + 1) >> 2, ac1 = ((tid * 2 + 1) & 3) * 4;
    const int wr  = tid >> 2,           wc  = (tid & 3) * 4;

    const float* Ag0 = A + (size_t)(row0 + ar0) * K + ac0;
    const float* Ag1 = A + (size_t)(row0 + ar1) * K + ac1;
    const float* Wg  = W + (size_t)(col0 + wr) * K + wc;

    const uint32_t as_base = smem_u32(As);
    const uint32_t ws_base = smem_u32(Ws);
    const uint32_t asz = BM * LDS_R * 4;
    const uint32_t wsz = BN * LDS_R * 4;
    const uint32_t ad0 = as_base + (ar0 * LDS_R + ac0) * 4;
    const uint32_t ad1 = as_base + (ar1 * LDS_R + ac1) * 4;
    const uint32_t wd  = ws_base + (wr * LDS_R + wc) * 4;

    const int T = K / BK;

    // prefetch tile 0
    cp_async16(ad0, Ag0);
    cp_async16(ad1, Ag1);
    cp_async16(wd, Wg);
    CP_COMMIT();

    float acc[2][4][4];
#pragma unroll
    for (int i = 0; i < 2; i++)
#pragma unroll
        for (int j = 0; j < 4; j++)
#pragma unroll
            for (int l = 0; l < 4; l++) acc[i][j][l] = 0.0f;

    for (int t = 0; t < T; t++) {
        const int cur = t & 1;
        if (t + 1 < T) {
            const int nxt = 1 - cur;
            const int k0 = (t + 1) * BK;
            cp_async16(ad0 + nxt * asz, Ag0 + k0);
            cp_async16(ad1 + nxt * asz, Ag1 + k0);
            cp_async16(wd + nxt * wsz, Wg + k0);
            CP_COMMIT();
            CP_WAIT(1);
        } else {
            CP_WAIT(0);
        }
        __syncthreads();

        const float* as = As[cur];
        const float* ws = Ws[cur];
#pragma unroll
        for (int kk = 0; kk < BK; kk += 8) {
            uint32_t af[2][4];
#pragma unroll
            for (int mt = 0; mt < 2; mt++) {
                const float* ap = as + (wm + mt * 16 + g) * LDS_R + kk + tin;
                af[mt][0] = to_tf32(ap[0]);
                af[mt][1] = to_tf32(ap[8 * LDS_R]);
                af[mt][2] = to_tf32(ap[4]);
                af[mt][3] = to_tf32(ap[8 * LDS_R + 4]);
            }
            uint32_t bf[4][2];
#pragma unroll
            for (int nt = 0; nt < 4; nt++) {
                const float* bp = ws + (wn + nt * 8 + g) * LDS_R + kk + tin;
                bf[nt][0] = to_tf32(bp[0]);
                bf[nt][1] = to_tf32(bp[4]);
            }
#pragma unroll
            for (int mt = 0; mt < 2; mt++)
#pragma unroll
                for (int nt = 0; nt < 4; nt++)
                    mma_tf32(acc[mt][nt], af[mt], bf[nt]);
        }
        __syncthreads();
    }

    // ---- epilogue: direct float2 stores per fragment layout ----
#pragma unroll
    for (int mt = 0; mt < 2; mt++) {
        const int r0 = row0 + wm + mt * 16 + g;
        const int r1 = r0 + 8;
        int d0 = r0, d1 = r1;
        if (EPI == 3) { d0 = src_index(r0); d1 = src_index(r1); }
#pragma unroll
        for (int nt = 0; nt < 4; nt++) {
            const int col = col0 + wn + nt * 8 + 2 * tin;
            const float2 bv = *(const float2*)&bias[col];
            float2 v0, v1;
            v0.x = acc[mt][nt][0] + bv.x;
            v0.y = acc[mt][nt][1] + bv.y;
            v1.x = acc[mt][nt][2] + bv.x;
            v1.y = acc[mt][nt][3] + bv.y;
            if (EPI == 1) {
                v0.x = gelu_exact(v0.x); v0.y = gelu_exact(v0.y);
                v1.x = gelu_exact(v1.x); v1.y = gelu_exact(v1.y);
            } else if (EPI == 2 || EPI == 3) {
                float2 q0 = *(const float2*)&res[(size_t)d0 * N + col];
                float2 q1 = *(const float2*)&res[(size_t)d1 * N + col];
                v0.x += q0.x; v0.y += q0.y;
                v1.x += q1.x; v1.y += q1.y;
            }
            *(float2*)&out[(size_t)d0 * N + col] = v0;
            *(float2*)&out[(size_t)d1 * N + col] = v1;
        }
    }
}

// ---------------------------------------------------------------------------
// Attention: one block per window; one warp per head.
// ---------------------------------------------------------------------------
#define QS 584
#define SS 52
#define ATTN_SMEM ((49 * QS + 6 * 49 * SS) * 4)

__global__ void attn_kernel(const float* __restrict__ qkv, float* __restrict__ o) {
    extern __shared__ float sm[];
    float* qk = sm;
    float* sc = sm + 49 * QS;

    const int w = blockIdx.x;
    const float* src = qkv + (size_t)w * (49 * 576);

    for (int idx = threadIdx.x; idx < 49 * 144; idx += blockDim.x) {
        int r = idx / 144, c = idx % 144;
        float4 v = *(const float4*)(src + r * 576 + c * 4);
        *(float4*)&qk[r * QS + c * 4] = v;
    }
    __syncthreads();

    const int warp = threadIdx.x >> 5;
    const int lane = threadIdx.x & 31;
    if (warp >= 6) return;
    const int h = warp;
    float* S = sc + h * 49 * SS;
    const float scale = 0.17677669529663687f;

#pragma unroll
    for (int jp = 0; jp < 2; jp++) {
        int j = jp * 32 + lane;
        if (j < 49) {
            float4 kr[8];
            const float* kb = qk + j * QS + 192 + h * 32;
#pragma unroll
            for (int t = 0; t < 8; t++) kr[t] = *(const float4*)(kb + t * 4);
            for (int i = 0; i < 49; i++) {
                const float* qb = qk + i * QS + h * 32;
                float s = 0.0f;
#pragma unroll
                for (int t = 0; t < 8; t++) {
                    float4 q4 = *(const float4*)(qb + t * 4);
                    s += q4.x * kr[t].x + q4.y * kr[t].y + q4.z * kr[t].z + q4.w * kr[t].w;
                }
                S[i * SS + j] = s * scale;
            }
        }
    }
    __syncwarp();

#pragma unroll
    for (int rp = 0; rp < 2; rp++) {
        int r = rp * 32 + lane;
        if (r < 49) {
            float* Sr = S + r * SS;
            float mx = Sr[0];
            for (int j = 1; j < 49; j++) mx = fmaxf(mx, Sr[j]);
            float sum = 0.0f;
            for (int j = 0; j < 49; j++) { float e = expf(Sr[j] - mx); Sr[j] = e; sum += e; }
            float inv = 1.0f / sum;
            for (int j = 0; j < 49; j++) Sr[j] *= inv;
        }
    }
    __syncwarp();

    float vr[49];
    const float* vb = qk + 384 + h * 32 + lane;
#pragma unroll
    for (int j = 0; j < 49; j++) vr[j] = vb[j * QS];

    float* ob = o + (size_t)w * (49 * 192) + h * 32 + lane;
    for (int i = 0; i < 49; i++) {
        const float* Si = S + i * SS;
        float a = 0.0f;
#pragma unroll 7
        for (int j = 0; j < 49; j++) a += Si[j] * vr[j];
        ob[i * 192] = a;
    }
}

// ---------------------------------------------------------------------------
// Launcher
// ---------------------------------------------------------------------------
extern "C" void kernel_launch(void* const* d_in, const int* in_sizes, int n_in,
                              void* d_out, int out_size) {
    const float* x     = (const float*)d_in[0];
    const float* ln1_g = (const float*)d_in[1];
    const float* ln1_b = (const float*)d_in[2];
    const float* ln2_g = (const float*)d_in[3];
    const float* ln2_b = (const float*)d_in[4];
    const float* w_qkv = (const float*)d_in[5];
    const float* b_qkv = (const float*)d_in[6];
    const float* w_out = (const float*)d_in[7];
    const float* b_out = (const float*)d_in[8];
    const float* w1    = (const float*)d_in[9];
    const float* b1    = (const float*)d_in[10];
    const float* w2    = (const float*)d_in[11];
    const float* b2    = (const float*)d_in[12];
    float* out = (float*)d_out;

    float *buf1, *buf2, *buf3;
    cudaGetSymbolAddress((void**)&buf1, g_buf1);
    cudaGetSymbolAddress((void**)&buf2, g_buf2);
    cudaGetSymbolAddress((void**)&buf3, g_buf3);

    cudaFuncSetAttribute(attn_kernel, cudaFuncAttributeMaxDynamicSharedMemorySize, ATTN_SMEM);

    const int MT = NTOK / BM;   // 784

    // 1) LN1 + shift + window partition -> buf1 (window order)
    ln_kernel<true><<<NTOK / 8, 256>>>(x, ln1_g, ln1_b, buf1);
    // 2) QKV GEMM -> buf2 [NTOK, 576]
    mma_gemm<0><<<dim3(576 / BN, MT), 256>>>(buf1, w_qkv, b_qkv, buf2, nullptr, 576, 192);
    // 3) windowed attention -> buf1 [NTOK, 192]
    attn_kernel<<<NWIN, 256, ATTN_SMEM>>>(buf2, buf1);
    // 4) proj + residual + unshift scatter -> buf3 (plain order)
    mma_gemm<3><<<dim3(192 / BN, MT), 256>>>(buf1, w_out, b_out, buf3, x, 192, 192);
    // 5) LN2 -> buf1
    ln_kernel<false><<<NTOK / 8, 256>>>(buf3, ln2_g, ln2_b, buf1);
    // 6) fc1 + GELU -> buf2 [NTOK, 384]
    mma_gemm<1><<<dim3(384 / BN, MT), 256>>>(buf1, w1, b1, buf2, nullptr, 384, 192);
    // 7) fc2 + residual -> d_out
    mma_gemm<2><<<dim3(192 / BN, MT), 256>>>(buf2, w2, b2, out, buf3, 192, 384);
}

// round 4
// speedup vs baseline: 2.0120x; 1.3776x over previous
#include <cuda_runtime.h>
#include <cuda_bf16.h>
#include <math.h>
#include <stdint.h>

// ---------------------------------------------------------------------------
// Swin block: B=32, H=W=56, D=192, HEADS=6, DH=32, WS=7, SHIFT=3, no pad,
// no attention mask (per reference).
// GEMMs: bf16 mma.sync m16n8k16 (fp32 accum), ldmatrix A-frags, 4-stage
// cp.async. Activations/weights bf16; residual path fp32.
// ---------------------------------------------------------------------------

#define NHW   3136
#define NTOK  100352
#define DIM   192
#define NWIN  2048

// bf16 activation buffers
__device__ __nv_bfloat16 g_a1 [(size_t)NTOK * DIM];   // LN1 out (window order)
__device__ __nv_bfloat16 g_qkv[(size_t)NTOK * 576];   // qkv
__device__ __nv_bfloat16 g_ao [(size_t)NTOK * DIM];   // attn out (window order)
__device__ float         g_x2 [(size_t)NTOK * DIM];   // residual x2 (fp32)
__device__ __nv_bfloat16 g_a2 [(size_t)NTOK * DIM];   // LN2 out
__device__ __nv_bfloat16 g_hid[(size_t)NTOK * 384];   // fc1 GELU out
// bf16 weights
__device__ __nv_bfloat16 g_wqkv[576 * 192];
__device__ __nv_bfloat16 g_wout[192 * 192];
__device__ __nv_bfloat16 g_w1  [384 * 192];
__device__ __nv_bfloat16 g_w2  [192 * 384];

__device__ __forceinline__ int src_index(int r) {
    int w = r / 49, p = r % 49;
    int b  = w >> 6;
    int wy = (w & 63) >> 3;
    int wx = w & 7;
    int py = p / 7, px = p % 7;
    int h2 = wy * 7 + py;
    int w2 = wx * 7 + px;
    int hs = h2 + 3; if (hs >= 56) hs -= 56;
    int ws = w2 + 3; if (ws >= 56) ws -= 56;
    return b * NHW + hs * 56 + ws;
}

// ---------------------------------------------------------------------------
// PTX helpers (sm_80+; safe on plain sm_100 ptxas target)
// ---------------------------------------------------------------------------
__device__ __forceinline__ uint32_t smem_u32(const void* p) {
    uint32_t a;
    asm("{ .reg .u64 t; cvta.to.shared.u64 t, %1; cvt.u32.u64 %0, t; }" : "=r"(a) : "l"(p));
    return a;
}
__device__ __forceinline__ void cp_async16(uint32_t dst, const void* src) {
    asm volatile("cp.async.ca.shared.global [%0], [%1], 16;" :: "r"(dst), "l"(src));
}
#define CP_COMMIT()  asm volatile("cp.async.commit_group;" ::: "memory")
#define CP_WAIT(n)   asm volatile("cp.async.wait_group %0;" :: "n"(n) : "memory")

__device__ __forceinline__ void ldsm4(uint32_t* r, uint32_t addr) {
    asm volatile("ldmatrix.sync.aligned.m8n8.x4.shared.b16 {%0,%1,%2,%3}, [%4];"
        : "=r"(r[0]), "=r"(r[1]), "=r"(r[2]), "=r"(r[3]) : "r"(addr));
}
__device__ __forceinline__ void mma_bf16(float* c, const uint32_t* a, const uint32_t* b) {
    asm volatile(
        "mma.sync.aligned.m16n8k16.row.col.f32.bf16.bf16.f32 "
        "{%0,%1,%2,%3}, {%4,%5,%6,%7}, {%8,%9}, {%0,%1,%2,%3};"
        : "+f"(c[0]), "+f"(c[1]), "+f"(c[2]), "+f"(c[3])
        : "r"(a[0]), "r"(a[1]), "r"(a[2]), "r"(a[3]), "r"(b[0]), "r"(b[1]));
}
__device__ __forceinline__ float gelu_exact(float v) {
    return 0.5f * v * (1.0f + erff(v * 0.7071067811865476f));
}

// ---------------------------------------------------------------------------
// Weight conversion fp32 -> bf16 (runs each launch; ~0.3M elements, trivial)
// ---------------------------------------------------------------------------
__global__ void wcvt(const float* __restrict__ wqkv, const float* __restrict__ wout,
                     const float* __restrict__ w1,   const float* __restrict__ w2) {
    int i = blockIdx.x * 256 + threadIdx.x;
    if (i < 110592)       g_wqkv[i]          = __float2bfloat16(wqkv[i]);
    else if (i < 147456)  g_wout[i - 110592] = __float2bfloat16(wout[i - 110592]);
    else if (i < 221184)  g_w1[i - 147456]   = __float2bfloat16(w1[i - 147456]);
    else if (i < 294912)  g_w2[i - 221184]   = __float2bfloat16(w2[i - 221184]);
}

// ---------------------------------------------------------------------------
// LayerNorm: one warp per token, fp32 in, bf16 out.
// ---------------------------------------------------------------------------
template <bool GATHER>
__global__ void ln_kernel(const float* __restrict__ x,
                          const float* __restrict__ gam,
                          const float* __restrict__ bet,
                          __nv_bfloat16* __restrict__ out) {
    int t    = blockIdx.x * 8 + (threadIdx.x >> 5);
    int lane = threadIdx.x & 31;
    int srow = GATHER ? src_index(t) : t;
    const float* xr = x + (size_t)srow * DIM;

    float v[6];
#pragma unroll
    for (int i = 0; i < 6; i++) v[i] = xr[lane + 32 * i];

    float s = v[0] + v[1] + v[2] + v[3] + v[4] + v[5];
#pragma unroll
    for (int o = 16; o; o >>= 1) s += __shfl_xor_sync(0xffffffffu, s, o);
    float mean = s * (1.0f / 192.0f);

    float q = 0.0f;
#pragma unroll
    for (int i = 0; i < 6; i++) { float d = v[i] - mean; q += d * d; }
#pragma unroll
    for (int o = 16; o; o >>= 1) q += __shfl_xor_sync(0xffffffffu, q, o);
    float rstd = rsqrtf(q * (1.0f / 192.0f) + 1e-5f);

    __nv_bfloat16* orow = out + (size_t)t * DIM;
#pragma unroll
    for (int i = 0; i < 6; i++) {
        int c = lane + 32 * i;
        orow[c] = __float2bfloat16((v[i] - mean) * rstd * gam[c] + bet[c]);
    }
}

// ---------------------------------------------------------------------------
// bf16 GEMM: C[M,N] = A[M,K] @ W[N,K]^T + bias (+epilogue)
// BM=128, BN=64, BK=16, 4-stage cp.async, 8 warps (4m x 2n), warp tile 32x32.
// SMEM row stride 24 bf16 (48 B) -> conflict-free ldmatrix & B LDS.
//   EPI 0: bf16 store               EPI 1: GELU, bf16 store
//   EPI 2: + res[row], fp32 store   EPI 3: + res[src(row)], fp32 scatter store
// ---------------------------------------------------------------------------
#define BM 128
#define BN 64
#define BK 16
#define STG 4
#define AROW 24                      // bf16 elems per smem row (48 B)

template <int EPI>
__global__ __launch_bounds__(256, 3)
void bgemm(const __nv_bfloat16* __restrict__ A, const __nv_bfloat16* __restrict__ W,
           const float* __restrict__ bias, void* __restrict__ outp,
           const float* __restrict__ res, int N, int K) {
    __shared__ __align__(16) __nv_bfloat16 As[STG][BM * AROW];
    __shared__ __align__(16) __nv_bfloat16 Ws[STG][BN * AROW];

    const int tid  = threadIdx.x;
    const int wid  = tid >> 5;
    const int lane = tid & 31;
    const int g    = lane >> 2;
    const int tin  = lane & 3;
    const int wm   = (wid & 3) * 32;
    const int wn   = (wid >> 2) * 32;
    const int row0 = blockIdx.y * BM;
    const int col0 = blockIdx.x * BN;

    // global->smem: 16B chunks (8 bf16). A: 256 chunks, B: 128 chunks.
    const int arow = tid >> 1, achk = tid & 1;
    const int brow = (tid & 127) >> 1, bchk = tid & 1;
    const bool bld = tid < 128;

    const __nv_bfloat16* Ag = A + (size_t)(row0 + arow) * K + achk * 8;
    const __nv_bfloat16* Wg = W + (size_t)(col0 + brow) * K + bchk * 8;
    const uint32_t asb = smem_u32(As) + (arow * AROW + achk * 8) * 2;
    const uint32_t wsb = smem_u32(Ws) + (brow * AROW + bchk * 8) * 2;
    const uint32_t ASZ = BM * AROW * 2;
    const uint32_t WSZ = BN * AROW * 2;

    const int T = K / BK;
#pragma unroll
    for (int s = 0; s < STG - 1; s++) {
        cp_async16(asb + s * ASZ, Ag + s * BK);
        if (bld) cp_async16(wsb + s * WSZ, Wg + s * BK);
        CP_COMMIT();
    }

    float acc[2][4][4];
#pragma unroll
    for (int i = 0; i < 2; i++)
#pragma unroll
        for (int j = 0; j < 4; j++)
#pragma unroll
            for (int l = 0; l < 4; l++) acc[i][j][l] = 0.0f;

    // ldmatrix lane address: row = wm + mt*16 + (lane&15), 16B-col = lane>>4
    const uint32_t albase = smem_u32(As) + ((wm + (lane & 15)) * AROW) * 2 + (lane >> 4) * 16;

    for (int t = 0; t < T; t++) {
        CP_WAIT(STG - 2);
        __syncthreads();
        const int tn = t + STG - 1;
        if (tn < T) {
            const int s = tn % STG;
            cp_async16(asb + s * ASZ, Ag + tn * BK);
            if (bld) cp_async16(wsb + s * WSZ, Wg + tn * BK);
        }
        CP_COMMIT();

        const int st = t % STG;
        uint32_t af[2][4];
        ldsm4(af[0], albase + st * ASZ);
        ldsm4(af[1], albase + st * ASZ + 16 * AROW * 2);

        uint32_t bf[4][2];
        const __nv_bfloat16* wsr = Ws[st];
#pragma unroll
        for (int nt = 0; nt < 4; nt++) {
            const __nv_bfloat16* bp = wsr + (wn + nt * 8 + g) * AROW + 2 * tin;
            bf[nt][0] = *(const uint32_t*)(bp);
            bf[nt][1] = *(const uint32_t*)(bp + 8);
        }
#pragma unroll
        for (int mt = 0; mt < 2; mt++)
#pragma unroll
            for (int nt = 0; nt < 4; nt++)
                mma_bf16(acc[mt][nt], af[mt], bf[nt]);
    }

    // ---- epilogue ----
    __nv_bfloat16* outb = (__nv_bfloat16*)outp;
    float*         outf = (float*)outp;
#pragma unroll
    for (int mt = 0; mt < 2; mt++) {
        const int r0 = row0 + wm + mt * 16 + g;
        const int r1 = r0 + 8;
        int d0 = r0, d1 = r1;
        if (EPI == 3) { d0 = src_index(r0); d1 = src_index(r1); }
#pragma unroll
        for (int nt = 0; nt < 4; nt++) {
            const int col = col0 + wn + nt * 8 + 2 * tin;
            const float2 bv = *(const float2*)&bias[col];
            float2 v0, v1;
            v0.x = acc[mt][nt][0] + bv.x;
            v0.y = acc[mt][nt][1] + bv.y;
            v1.x = acc[mt][nt][2] + bv.x;
            v1.y = acc[mt][nt][3] + bv.y;
            if (EPI == 1) {
                v0.x = gelu_exact(v0.x); v0.y = gelu_exact(v0.y);
                v1.x = gelu_exact(v1.x); v1.y = gelu_exact(v1.y);
            }
            if (EPI == 0 || EPI == 1) {
                *(__nv_bfloat162*)&outb[(size_t)d0 * N + col] = __floats2bfloat162_rn(v0.x, v0.y);
                *(__nv_bfloat162*)&outb[(size_t)d1 * N + col] = __floats2bfloat162_rn(v1.x, v1.y);
            } else {
                float2 q0 = *(const float2*)&res[(size_t)d0 * N + col];
                float2 q1 = *(const float2*)&res[(size_t)d1 * N + col];
                v0.x += q0.x; v0.y += q0.y;
                v1.x += q1.x; v1.y += q1.y;
                *(float2*)&outf[(size_t)d0 * N + col] = v0;
                *(float2*)&outf[(size_t)d1 * N + col] = v1;
            }
        }
    }
}

// ---------------------------------------------------------------------------
// Attention: one block per window; one warp per head. bf16 in/out, fp32 math.
// ---------------------------------------------------------------------------
#define QS 584
#define SS 52
#define ATTN_SMEM ((49 * QS + 6 * 49 * SS) * 4)

__global__ void attn_kernel(const __nv_bfloat16* __restrict__ qkv,
                            __nv_bfloat16* __restrict__ o) {
    extern __shared__ float sm[];
    float* qk = sm;
    float* sc = sm + 49 * QS;

    const int w = blockIdx.x;
    const __nv_bfloat16* src = qkv + (size_t)w * (49 * 576);

    for (int idx = threadIdx.x; idx < 49 * 72; idx += blockDim.x) {
        int r = idx / 72, c = idx % 72;
        uint4 raw = *(const uint4*)(src + r * 576 + c * 8);
        const __nv_bfloat162* h = (const __nv_bfloat162*)&raw;
        float* dst = &qk[r * QS + c * 8];
#pragma unroll
        for (int j = 0; j < 4; j++) {
            float2 f = __bfloat1622float2(h[j]);
            dst[2 * j]     = f.x;
            dst[2 * j + 1] = f.y;
        }
    }
    __syncthreads();

    const int warp = threadIdx.x >> 5;
    const int lane = threadIdx.x & 31;
    if (warp >= 6) return;
    const int h = warp;
    float* S = sc + h * 49 * SS;
    const float scale = 0.17677669529663687f;

#pragma unroll
    for (int jp = 0; jp < 2; jp++) {
        int j = jp * 32 + lane;
        if (j < 49) {
            float4 kr[8];
            const float* kb = qk + j * QS + 192 + h * 32;
#pragma unroll
            for (int t = 0; t < 8; t++) kr[t] = *(const float4*)(kb + t * 4);
            for (int i = 0; i < 49; i++) {
                const float* qb = qk + i * QS + h * 32;
                float s = 0.0f;
#pragma unroll
                for (int t = 0; t < 8; t++) {
                    float4 q4 = *(const float4*)(qb + t * 4);
                    s += q4.x * kr[t].x + q4.y * kr[t].y + q4.z * kr[t].z + q4.w * kr[t].w;
                }
                S[i * SS + j] = s * scale;
            }
        }
    }
    __syncwarp();

#pragma unroll
    for (int rp = 0; rp < 2; rp++) {
        int r = rp * 32 + lane;
        if (r < 49) {
            float* Sr = S + r * SS;
            float mx = Sr[0];
            for (int j = 1; j < 49; j++) mx = fmaxf(mx, Sr[j]);
            float sum = 0.0f;
            for (int j = 0; j < 49; j++) { float e = expf(Sr[j] - mx); Sr[j] = e; sum += e; }
            float inv = 1.0f / sum;
            for (int j = 0; j < 49; j++) Sr[j] *= inv;
        }
    }
    __syncwarp();

    float vr[49];
    const float* vb = qk + 384 + h * 32 + lane;
#pragma unroll
    for (int j = 0; j < 49; j++) vr[j] = vb[j * QS];

    __nv_bfloat16* ob = o + (size_t)w * (49 * 192) + h * 32 + lane;
    for (int i = 0; i < 49; i++) {
        const float* Si = S + i * SS;
        float a = 0.0f;
#pragma unroll 7
        for (int j = 0; j < 49; j++) a += Si[j] * vr[j];
        ob[i * 192] = __float2bfloat16(a);
    }
}

// ---------------------------------------------------------------------------
// Launcher
// ---------------------------------------------------------------------------
extern "C" void kernel_launch(void* const* d_in, const int* in_sizes, int n_in,
                              void* d_out, int out_size) {
    const float* x     = (const float*)d_in[0];
    const float* ln1_g = (const float*)d_in[1];
    const float* ln1_b = (const float*)d_in[2];
    const float* ln2_g = (const float*)d_in[3];
    const float* ln2_b = (const float*)d_in[4];
    const float* w_qkv = (const float*)d_in[5];
    const float* b_qkv = (const float*)d_in[6];
    const float* w_out = (const float*)d_in[7];
    const float* b_out = (const float*)d_in[8];
    const float* w1    = (const float*)d_in[9];
    const float* b1    = (const float*)d_in[10];
    const float* w2    = (const float*)d_in[11];
    const float* b2    = (const float*)d_in[12];
    float* out = (float*)d_out;

    __nv_bfloat16 *a1, *qkvb, *aob, *a2, *hid, *wq, *wo, *ww1, *ww2;
    float* x2;
    cudaGetSymbolAddress((void**)&a1,   g_a1);
    cudaGetSymbolAddress((void**)&qkvb, g_qkv);
    cudaGetSymbolAddress((void**)&aob,  g_ao);
    cudaGetSymbolAddress((void**)&x2,   g_x2);
    cudaGetSymbolAddress((void**)&a2,   g_a2);
    cudaGetSymbolAddress((void**)&hid,  g_hid);
    cudaGetSymbolAddress((void**)&wq,   g_wqkv);
    cudaGetSymbolAddress((void**)&wo,   g_wout);
    cudaGetSymbolAddress((void**)&ww1,  g_w1);
    cudaGetSymbolAddress((void**)&ww2,  g_w2);

    cudaFuncSetAttribute(attn_kernel, cudaFuncAttributeMaxDynamicSharedMemorySize, ATTN_SMEM);

    const int MT = NTOK / BM;   // 784

    // 0) weights fp32 -> bf16
    wcvt<<<1152, 256>>>(w_qkv, w_out, w1, w2);
    // 1) LN1 + shift + window partition -> a1 (bf16, window order)
    ln_kernel<true><<<NTOK / 8, 256>>>(x, ln1_g, ln1_b, a1);
    // 2) QKV GEMM -> qkvb [NTOK, 576] bf16
    bgemm<0><<<dim3(9, MT), 256>>>(a1, wq, b_qkv, qkvb, nullptr, 576, 192);
    // 3) windowed attention -> aob [NTOK, 192] bf16
    attn_kernel<<<NWIN, 256, ATTN_SMEM>>>(qkvb, aob);
    // 4) proj + residual + unshift scatter -> x2 (fp32, plain order)
    bgemm<3><<<dim3(3, MT), 256>>>(aob, wo, b_out, x2, x, 192, 192);
    // 5) LN2 -> a2 (bf16)
    ln_kernel<false><<<NTOK / 8, 256>>>(x2, ln2_g, ln2_b, a2);
    // 6) fc1 + GELU -> hid [NTOK, 384] bf16
    bgemm<1><<<dim3(6, MT), 256>>>(a2, ww1, b1, hid, nullptr, 384, 192);
    // 7) fc2 + residual -> d_out fp32
    bgemm<2><<<dim3(3, MT), 256>>>(hid, ww2, b2, out, x2, 192, 384);
}

// round 5
// speedup vs baseline: 3.7188x; 1.8483x over previous
#include <cuda_runtime.h>
#include <cuda_bf16.h>
#include <math.h>
#include <stdint.h>

// ---------------------------------------------------------------------------
// Swin block: B=32, H=W=56, D=192, HEADS=6, DH=32, WS=7, SHIFT=3, no pad,
// no attention mask (per reference).
// GEMMs: bf16 mma.sync m16n8k16 + cp.async (round 4).
// Attention: NEW tensor-core window attention, register softmax.
// ---------------------------------------------------------------------------

#define NHW   3136
#define NTOK  100352
#define DIM   192
#define NWIN  2048

__device__ __nv_bfloat16 g_a1 [(size_t)NTOK * DIM];
__device__ __nv_bfloat16 g_qkv[(size_t)NTOK * 576];
__device__ __nv_bfloat16 g_ao [(size_t)NTOK * DIM];
__device__ float         g_x2 [(size_t)NTOK * DIM];
__device__ __nv_bfloat16 g_a2 [(size_t)NTOK * DIM];
__device__ __nv_bfloat16 g_hid[(size_t)NTOK * 384];
__device__ __nv_bfloat16 g_wqkv[576 * 192];
__device__ __nv_bfloat16 g_wout[192 * 192];
__device__ __nv_bfloat16 g_w1  [384 * 192];
__device__ __nv_bfloat16 g_w2  [192 * 384];

__device__ __forceinline__ int src_index(int r) {
    int w = r / 49, p = r % 49;
    int b  = w >> 6;
    int wy = (w & 63) >> 3;
    int wx = w & 7;
    int py = p / 7, px = p % 7;
    int h2 = wy * 7 + py;
    int w2 = wx * 7 + px;
    int hs = h2 + 3; if (hs >= 56) hs -= 56;
    int ws = w2 + 3; if (ws >= 56) ws -= 56;
    return b * NHW + hs * 56 + ws;
}

// ---------------------------------------------------------------------------
// PTX helpers (sm_80+; safe on plain sm_100 ptxas target)
// ---------------------------------------------------------------------------
__device__ __forceinline__ uint32_t smem_u32(const void* p) {
    uint32_t a;
    asm("{ .reg .u64 t; cvta.to.shared.u64 t, %1; cvt.u32.u64 %0, t; }" : "=r"(a) : "l"(p));
    return a;
}
__device__ __forceinline__ void cp_async16(uint32_t dst, const void* src) {
    asm volatile("cp.async.ca.shared.global [%0], [%1], 16;" :: "r"(dst), "l"(src));
}
#define CP_COMMIT()  asm volatile("cp.async.commit_group;" ::: "memory")
#define CP_WAIT(n)   asm volatile("cp.async.wait_group %0;" :: "n"(n) : "memory")

__device__ __forceinline__ void ldsm4(uint32_t* r, uint32_t addr) {
    asm volatile("ldmatrix.sync.aligned.m8n8.x4.shared.b16 {%0,%1,%2,%3}, [%4];"
        : "=r"(r[0]), "=r"(r[1]), "=r"(r[2]), "=r"(r[3]) : "r"(addr));
}
__device__ __forceinline__ void ldsm2(uint32_t* r, uint32_t addr) {
    asm volatile("ldmatrix.sync.aligned.m8n8.x2.shared.b16 {%0,%1}, [%2];"
        : "=r"(r[0]), "=r"(r[1]) : "r"(addr));
}
__device__ __forceinline__ void ldsm2t(uint32_t* r, uint32_t addr) {
    asm volatile("ldmatrix.sync.aligned.m8n8.x2.trans.shared.b16 {%0,%1}, [%2];"
        : "=r"(r[0]), "=r"(r[1]) : "r"(addr));
}
__device__ __forceinline__ void mma_bf16(float* c, const uint32_t* a, const uint32_t* b) {
    asm volatile(
        "mma.sync.aligned.m16n8k16.row.col.f32.bf16.bf16.f32 "
        "{%0,%1,%2,%3}, {%4,%5,%6,%7}, {%8,%9}, {%0,%1,%2,%3};"
        : "+f"(c[0]), "+f"(c[1]), "+f"(c[2]), "+f"(c[3])
        : "r"(a[0]), "r"(a[1]), "r"(a[2]), "r"(a[3]), "r"(b[0]), "r"(b[1]));
}
__device__ __forceinline__ float gelu_exact(float v) {
    return 0.5f * v * (1.0f + erff(v * 0.7071067811865476f));
}
__device__ __forceinline__ uint32_t packbf(float a, float b) {
    __nv_bfloat162 t = __floats2bfloat162_rn(a, b);
    return *(uint32_t*)&t;
}

// ---------------------------------------------------------------------------
// Weight conversion fp32 -> bf16
// ---------------------------------------------------------------------------
__global__ void wcvt(const float* __restrict__ wqkv, const float* __restrict__ wout,
                     const float* __restrict__ w1,   const float* __restrict__ w2) {
    int i = blockIdx.x * 256 + threadIdx.x;
    if (i < 110592)       g_wqkv[i]          = __float2bfloat16(wqkv[i]);
    else if (i < 147456)  g_wout[i - 110592] = __float2bfloat16(wout[i - 110592]);
    else if (i < 221184)  g_w1[i - 147456]   = __float2bfloat16(w1[i - 147456]);
    else if (i < 294912)  g_w2[i - 221184]   = __float2bfloat16(w2[i - 221184]);
}

// ---------------------------------------------------------------------------
// LayerNorm: one warp per token, fp32 in, bf16 out.
// ---------------------------------------------------------------------------
template <bool GATHER>
__global__ void ln_kernel(const float* __restrict__ x,
                          const float* __restrict__ gam,
                          const float* __restrict__ bet,
                          __nv_bfloat16* __restrict__ out) {
    int t    = blockIdx.x * 8 + (threadIdx.x >> 5);
    int lane = threadIdx.x & 31;
    int srow = GATHER ? src_index(t) : t;
    const float* xr = x + (size_t)srow * DIM;

    float v[6];
#pragma unroll
    for (int i = 0; i < 6; i++) v[i] = xr[lane + 32 * i];

    float s = v[0] + v[1] + v[2] + v[3] + v[4] + v[5];
#pragma unroll
    for (int o = 16; o; o >>= 1) s += __shfl_xor_sync(0xffffffffu, s, o);
    float mean = s * (1.0f / 192.0f);

    float q = 0.0f;
#pragma unroll
    for (int i = 0; i < 6; i++) { float d = v[i] - mean; q += d * d; }
#pragma unroll
    for (int o = 16; o; o >>= 1) q += __shfl_xor_sync(0xffffffffu, q, o);
    float rstd = rsqrtf(q * (1.0f / 192.0f) + 1e-5f);

    __nv_bfloat16* orow = out + (size_t)t * DIM;
#pragma unroll
    for (int i = 0; i < 6; i++) {
        int c = lane + 32 * i;
        orow[c] = __float2bfloat16((v[i] - mean) * rstd * gam[c] + bet[c]);
    }
}

// ---------------------------------------------------------------------------
// bf16 GEMM (round 4, unchanged)
// ---------------------------------------------------------------------------
#define BM 128
#define BN 64
#define BK 16
#define STG 4
#define AROW 24

template <int EPI>
__global__ __launch_bounds__(256, 3)
void bgemm(const __nv_bfloat16* __restrict__ A, const __nv_bfloat16* __restrict__ W,
           const float* __restrict__ bias, void* __restrict__ outp,
           const float* __restrict__ res, int N, int K) {
    __shared__ __align__(16) __nv_bfloat16 As[STG][BM * AROW];
    __shared__ __align__(16) __nv_bfloat16 Ws[STG][BN * AROW];

    const int tid  = threadIdx.x;
    const int wid  = tid >> 5;
    const int lane = tid & 31;
    const int g    = lane >> 2;
    const int tin  = lane & 3;
    const int wm   = (wid & 3) * 32;
    const int wn   = (wid >> 2) * 32;
    const int row0 = blockIdx.y * BM;
    const int col0 = blockIdx.x * BN;

    const int arow = tid >> 1, achk = tid & 1;
    const int brow = (tid & 127) >> 1, bchk = tid & 1;
    const bool bld = tid < 128;

    const __nv_bfloat16* Ag = A + (size_t)(row0 + arow) * K + achk * 8;
    const __nv_bfloat16* Wg = W + (size_t)(col0 + brow) * K + bchk * 8;
    const uint32_t asb = smem_u32(As) + (arow * AROW + achk * 8) * 2;
    const uint32_t wsb = smem_u32(Ws) + (brow * AROW + bchk * 8) * 2;
    const uint32_t ASZ = BM * AROW * 2;
    const uint32_t WSZ = BN * AROW * 2;

    const int T = K / BK;
#pragma unroll
    for (int s = 0; s < STG - 1; s++) {
        cp_async16(asb + s * ASZ, Ag + s * BK);
        if (bld) cp_async16(wsb + s * WSZ, Wg + s * BK);
        CP_COMMIT();
    }

    float acc[2][4][4];
#pragma unroll
    for (int i = 0; i < 2; i++)
#pragma unroll
        for (int j = 0; j < 4; j++)
#pragma unroll
            for (int l = 0; l < 4; l++) acc[i][j][l] = 0.0f;

    const uint32_t albase = smem_u32(As) + ((wm + (lane & 15)) * AROW) * 2 + (lane >> 4) * 16;

    for (int t = 0; t < T; t++) {
        CP_WAIT(STG - 2);
        __syncthreads();
        const int tn = t + STG - 1;
        if (tn < T) {
            const int s = tn % STG;
            cp_async16(asb + s * ASZ, Ag + tn * BK);
            if (bld) cp_async16(wsb + s * WSZ, Wg + tn * BK);
        }
        CP_COMMIT();

        const int st = t % STG;
        uint32_t af[2][4];
        ldsm4(af[0], albase + st * ASZ);
        ldsm4(af[1], albase + st * ASZ + 16 * AROW * 2);

        uint32_t bf[4][2];
        const __nv_bfloat16* wsr = Ws[st];
#pragma unroll
        for (int nt = 0; nt < 4; nt++) {
            const __nv_bfloat16* bp = wsr + (wn + nt * 8 + g) * AROW + 2 * tin;
            bf[nt][0] = *(const uint32_t*)(bp);
            bf[nt][1] = *(const uint32_t*)(bp + 8);
        }
#pragma unroll
        for (int mt = 0; mt < 2; mt++)
#pragma unroll
            for (int nt = 0; nt < 4; nt++)
                mma_bf16(acc[mt][nt], af[mt], bf[nt]);
    }

    __nv_bfloat16* outb = (__nv_bfloat16*)outp;
    float*         outf = (float*)outp;
#pragma unroll
    for (int mt = 0; mt < 2; mt++) {
        const int r0 = row0 + wm + mt * 16 + g;
        const int r1 = r0 + 8;
        int d0 = r0, d1 = r1;
        if (EPI == 3) { d0 = src_index(r0); d1 = src_index(r1); }
#pragma unroll
        for (int nt = 0; nt < 4; nt++) {
            const int col = col0 + wn + nt * 8 + 2 * tin;
            const float2 bv = *(const float2*)&bias[col];
            float2 v0, v1;
            v0.x = acc[mt][nt][0] + bv.x;
            v0.y = acc[mt][nt][1] + bv.y;
            v1.x = acc[mt][nt][2] + bv.x;
            v1.y = acc[mt][nt][3] + bv.y;
            if (EPI == 1) {
                v0.x = gelu_exact(v0.x); v0.y = gelu_exact(v0.y);
                v1.x = gelu_exact(v1.x); v1.y = gelu_exact(v1.y);
            }
            if (EPI == 0 || EPI == 1) {
                *(__nv_bfloat162*)&outb[(size_t)d0 * N + col] = __floats2bfloat162_rn(v0.x, v0.y);
                *(__nv_bfloat162*)&outb[(size_t)d1 * N + col] = __floats2bfloat162_rn(v1.x, v1.y);
            } else {
                float2 q0 = *(const float2*)&res[(size_t)d0 * N + col];
                float2 q1 = *(const float2*)&res[(size_t)d1 * N + col];
                v0.x += q0.x; v0.y += q0.y;
                v1.x += q1.x; v1.y += q1.y;
                *(float2*)&outf[(size_t)d0 * N + col] = v0;
                *(float2*)&outf[(size_t)d1 * N + col] = v1;
            }
        }
    }
}

// ---------------------------------------------------------------------------
// Tensor-core window attention.
// Block = 384 threads = 12 warps = one window; warp (h, half): 2 warps/head.
// QKV bf16 smem [64][584] (rows 49-63 zeroed); S & softmax in registers;
// P fragments reused directly as A-operand of P@V.
// ---------------------------------------------------------------------------
#define AQS   584                      // bf16 row stride (1168 B)
#define ATTN_SMEM (64 * AQS * 2)       // 74752 B

__global__ __launch_bounds__(384, 2)
void attn_mma(const __nv_bfloat16* __restrict__ qkv, __nv_bfloat16* __restrict__ o) {
    extern __shared__ __nv_bfloat16 sq[];
    const int w   = blockIdx.x;
    const int tid = threadIdx.x;

    // stage window QKV (49 rows x 576) into [64][584] smem, zero pad rows
    const __nv_bfloat16* src = qkv + (size_t)w * (49 * 576);
    for (int idx = tid; idx < 49 * 72; idx += 384) {
        int r = idx / 72, c = idx % 72;
        *(uint4*)&sq[r * AQS + c * 8] = *(const uint4*)(src + r * 576 + c * 8);
    }
    for (int idx = tid; idx < 15 * 73; idx += 384) {
        int r = 49 + idx / 73, c = idx % 73;
        *(uint4*)&sq[r * AQS + c * 8] = make_uint4(0, 0, 0, 0);
    }
    __syncthreads();

    const int warp = tid >> 5;
    const int lane = tid & 31;
    const int h    = warp >> 1;          // head 0..5
    const int wm   = (warp & 1) * 32;    // row half
    const int g    = lane >> 2;
    const int tin  = lane & 3;
    const uint32_t sqb = smem_u32(sq);
    const int l15 = lane & 15, lhi = lane >> 4;

    // ---- S = Q @ K^T (2 m-tiles x 7 n-tiles, K=32) ----
    float acc[2][7][4];
#pragma unroll
    for (int mt = 0; mt < 2; mt++)
#pragma unroll
        for (int nt = 0; nt < 7; nt++)
#pragma unroll
            for (int c = 0; c < 4; c++) acc[mt][nt][c] = 0.0f;

#pragma unroll
    for (int kc = 0; kc < 2; kc++) {
        uint32_t qa[2][4];
#pragma unroll
        for (int mt = 0; mt < 2; mt++) {
            uint32_t addr = sqb + (uint32_t)(wm + mt * 16 + l15) * (AQS * 2)
                          + (h * 32 + kc * 16) * 2 + lhi * 16;
            ldsm4(qa[mt], addr);
        }
#pragma unroll
        for (int nt = 0; nt < 7; nt++) {
            uint32_t kb[2];
            uint32_t kaddr = sqb + (uint32_t)(nt * 8 + (lane & 7)) * (AQS * 2)
                           + (192 + h * 32 + kc * 16) * 2 + ((lane >> 3) & 1) * 16;
            ldsm2(kb, kaddr);
            mma_bf16(acc[0][nt], qa[0], kb);
            mma_bf16(acc[1][nt], qa[1], kb);
        }
    }

    // ---- softmax in registers (rows = wm+mt*16+g and +8; cols nt*8+2tin+{0,1}) ----
    const float scale = 0.17677669529663687f;   // 1/sqrt(32)
    float sums[2][2];
    uint32_t pk[2][8][2];
#pragma unroll
    for (int mt = 0; mt < 2; mt++) {
        float mx0 = -1e30f, mx1 = -1e30f;
#pragma unroll
        for (int nt = 0; nt < 7; nt++) {
            int c0 = nt * 8 + 2 * tin;
            float* a = acc[mt][nt];
            a[0] = (c0     < 49) ? a[0] * scale : -1e30f;
            a[1] = (c0 + 1 < 49) ? a[1] * scale : -1e30f;
            a[2] = (c0     < 49) ? a[2] * scale : -1e30f;
            a[3] = (c0 + 1 < 49) ? a[3] * scale : -1e30f;
            mx0 = fmaxf(mx0, fmaxf(a[0], a[1]));
            mx1 = fmaxf(mx1, fmaxf(a[2], a[3]));
        }
        mx0 = fmaxf(mx0, __shfl_xor_sync(0xffffffffu, mx0, 1));
        mx0 = fmaxf(mx0, __shfl_xor_sync(0xffffffffu, mx0, 2));
        mx1 = fmaxf(mx1, __shfl_xor_sync(0xffffffffu, mx1, 1));
        mx1 = fmaxf(mx1, __shfl_xor_sync(0xffffffffu, mx1, 2));
        float s0 = 0.0f, s1 = 0.0f;
#pragma unroll
        for (int nt = 0; nt < 7; nt++) {
            float* a = acc[mt][nt];
            a[0] = __expf(a[0] - mx0);
            a[1] = __expf(a[1] - mx0);
            a[2] = __expf(a[2] - mx1);
            a[3] = __expf(a[3] - mx1);
            s0 += a[0] + a[1];
            s1 += a[2] + a[3];
            pk[mt][nt][0] = packbf(a[0], a[1]);
            pk[mt][nt][1] = packbf(a[2], a[3]);
        }
        pk[mt][7][0] = 0u;
        pk[mt][7][1] = 0u;
        s0 += __shfl_xor_sync(0xffffffffu, s0, 1);
        s0 += __shfl_xor_sync(0xffffffffu, s0, 2);
        s1 += __shfl_xor_sync(0xffffffffu, s1, 1);
        s1 += __shfl_xor_sync(0xffffffffu, s1, 2);
        sums[mt][0] = s0;
        sums[mt][1] = s1;
    }

    // ---- O = P @ V (K = 64 padded; P cols 49-63 are zero) ----
    float pv[2][4][4];
#pragma unroll
    for (int mt = 0; mt < 2; mt++)
#pragma unroll
        for (int nt = 0; nt < 4; nt++)
#pragma unroll
            for (int c = 0; c < 4; c++) pv[mt][nt][c] = 0.0f;

#pragma unroll
    for (int kc = 0; kc < 4; kc++) {
        uint32_t pa[2][4];
#pragma unroll
        for (int mt = 0; mt < 2; mt++) {
            pa[mt][0] = pk[mt][2 * kc][0];
            pa[mt][1] = pk[mt][2 * kc][1];
            pa[mt][2] = pk[mt][2 * kc + 1][0];
            pa[mt][3] = pk[mt][2 * kc + 1][1];
        }
#pragma unroll
        for (int nt = 0; nt < 4; nt++) {
            uint32_t vb[2];
            uint32_t vaddr = sqb + (uint32_t)(kc * 16 + l15) * (AQS * 2)
                           + (384 + h * 32 + nt * 8) * 2;
            ldsm2t(vb, vaddr);
            mma_bf16(pv[0][nt], pa[0], vb);
            mma_bf16(pv[1][nt], pa[1], vb);
        }
    }

    // ---- store O (normalize by row sums) ----
    __nv_bfloat16* ob = o + (size_t)w * (49 * 192);
#pragma unroll
    for (int mt = 0; mt < 2; mt++) {
        const int r0 = wm + mt * 16 + g;
        const int r1 = r0 + 8;
        const float inv0 = 1.0f / sums[mt][0];
        const float inv1 = 1.0f / sums[mt][1];
#pragma unroll
        for (int nt = 0; nt < 4; nt++) {
            const int col = h * 32 + nt * 8 + 2 * tin;
            if (r0 < 49)
                *(uint32_t*)&ob[r0 * 192 + col] = packbf(pv[mt][nt][0] * inv0, pv[mt][nt][1] * inv0);
            if (r1 < 49)
                *(uint32_t*)&ob[r1 * 192 + col] = packbf(pv[mt][nt][2] * inv1, pv[mt][nt][3] * inv1);
        }
    }
}

// ---------------------------------------------------------------------------
// Launcher
// ---------------------------------------------------------------------------
extern "C" void kernel_launch(void* const* d_in, const int* in_sizes, int n_in,
                              void* d_out, int out_size) {
    const float* x     = (const float*)d_in[0];
    const float* ln1_g = (const float*)d_in[1];
    const float* ln1_b = (const float*)d_in[2];
    const float* ln2_g = (const float*)d_in[3];
    const float* ln2_b = (const float*)d_in[4];
    const float* w_qkv = (const float*)d_in[5];
    const float* b_qkv = (const float*)d_in[6];
    const float* w_out = (const float*)d_in[7];
    const float* b_out = (const float*)d_in[8];
    const float* w1    = (const float*)d_in[9];
    const float* b1    = (const float*)d_in[10];
    const float* w2    = (const float*)d_in[11];
    const float* b2    = (const float*)d_in[12];
    float* out = (float*)d_out;

    __nv_bfloat16 *a1, *qkvb, *aob, *a2, *hid, *wq, *wo, *ww1, *ww2;
    float* x2;
    cudaGetSymbolAddress((void**)&a1,   g_a1);
    cudaGetSymbolAddress((void**)&qkvb, g_qkv);
    cudaGetSymbolAddress((void**)&aob,  g_ao);
    cudaGetSymbolAddress((void**)&x2,   g_x2);
    cudaGetSymbolAddress((void**)&a2,   g_a2);
    cudaGetSymbolAddress((void**)&hid,  g_hid);
    cudaGetSymbolAddress((void**)&wq,   g_wqkv);
    cudaGetSymbolAddress((void**)&wo,   g_wout);
    cudaGetSymbolAddress((void**)&ww1,  g_w1);
    cudaGetSymbolAddress((void**)&ww2,  g_w2);

    cudaFuncSetAttribute(attn_mma, cudaFuncAttributeMaxDynamicSharedMemorySize, ATTN_SMEM);

    const int MT = NTOK / BM;   // 784

    wcvt<<<1152, 256>>>(w_qkv, w_out, w1, w2);
    ln_kernel<true><<<NTOK / 8, 256>>>(x, ln1_g, ln1_b, a1);
    bgemm<0><<<dim3(9, MT), 256>>>(a1, wq, b_qkv, qkvb, nullptr, 576, 192);
    attn_mma<<<NWIN, 384, ATTN_SMEM>>>(qkvb, aob);
    bgemm<3><<<dim3(3, MT), 256>>>(aob, wo, b_out, x2, x, 192, 192);
    ln_kernel<false><<<NTOK / 8, 256>>>(x2, ln2_g, ln2_b, a2);
    bgemm<1><<<dim3(6, MT), 256>>>(a2, ww1, b1, hid, nullptr, 384, 192);
    bgemm<2><<<dim3(3, MT), 256>>>(hid, ww2, b2, out, x2, 192, 384);
}

// round 6
// speedup vs baseline: 4.1367x; 1.1124x over previous
#include <cuda_runtime.h>
#include <cuda_bf16.h>
#include <math.h>
#include <stdint.h>

// ---------------------------------------------------------------------------
// Swin block: B=32, H=W=56, D=192, HEADS=6, DH=32, WS=7, SHIFT=3, no pad,
// no attention mask (per reference).
// R6: QKV GEMM + attention fused into one kernel (qkv never hits DRAM);
//     LN2 folded into fc1 via gamma-folded weights + per-token stats from
//     the proj epilogue.
// ---------------------------------------------------------------------------

#define NHW   3136
#define NTOK  100352
#define DIM   192
#define NWIN  2048

__device__ __nv_bfloat16 g_a1 [(size_t)NTOK * DIM];   // LN1 out (window order)
__device__ __nv_bfloat16 g_ao [(size_t)NTOK * DIM];   // attn out (window order)
__device__ float         g_x2 [(size_t)NTOK * DIM];   // x2 fp32 (plain order)
__device__ __nv_bfloat16 g_x2b[(size_t)NTOK * DIM];   // x2 bf16 (plain order)
__device__ __nv_bfloat16 g_hid[(size_t)NTOK * 384];   // fc1 GELU out
__device__ __nv_bfloat16 g_wqkv[576 * 192];
__device__ __nv_bfloat16 g_wout[192 * 192];
__device__ __nv_bfloat16 g_w1  [384 * 192];           // gamma2-folded
__device__ __nv_bfloat16 g_w2  [192 * 384];
__device__ float2        g_st1 [384];                 // (S_n, T_n) for fc1 affine
__device__ float2        g_pbuf[6 * NTOK];            // per-slot (sum, sumsq)
__device__ float2        g_mstat[NTOK];               // (mean, rstd) of x2
__device__ __align__(16) __nv_bfloat16 g_zbuf[16];    // zero page for A padding

__device__ __forceinline__ int src_index(int r) {
    int w = r / 49, p = r % 49;
    int b  = w >> 6;
    int wy = (w & 63) >> 3;
    int wx = w & 7;
    int py = p / 7, px = p % 7;
    int h2 = wy * 7 + py;
    int w2 = wx * 7 + px;
    int hs = h2 + 3; if (hs >= 56) hs -= 56;
    int ws = w2 + 3; if (ws >= 56) ws -= 56;
    return b * NHW + hs * 56 + ws;
}

// ---------------------------------------------------------------------------
// PTX helpers (sm_80+; safe on plain sm_100 ptxas target)
// ---------------------------------------------------------------------------
__device__ __forceinline__ uint32_t smem_u32(const void* p) {
    uint32_t a;
    asm("{ .reg .u64 t; cvta.to.shared.u64 t, %1; cvt.u32.u64 %0, t; }" : "=r"(a) : "l"(p));
    return a;
}
__device__ __forceinline__ void cp_async16(uint32_t dst, const void* src) {
    asm volatile("cp.async.ca.shared.global [%0], [%1], 16;" :: "r"(dst), "l"(src));
}
#define CP_COMMIT()  asm volatile("cp.async.commit_group;" ::: "memory")
#define CP_WAIT(n)   asm volatile("cp.async.wait_group %0;" :: "n"(n) : "memory")

__device__ __forceinline__ void ldsm4(uint32_t* r, uint32_t addr) {
    asm volatile("ldmatrix.sync.aligned.m8n8.x4.shared.b16 {%0,%1,%2,%3}, [%4];"
        : "=r"(r[0]), "=r"(r[1]), "=r"(r[2]), "=r"(r[3]) : "r"(addr));
}
__device__ __forceinline__ void ldsm2(uint32_t* r, uint32_t addr) {
    asm volatile("ldmatrix.sync.aligned.m8n8.x2.shared.b16 {%0,%1}, [%2];"
        : "=r"(r[0]), "=r"(r[1]) : "r"(addr));
}
__device__ __forceinline__ void ldsm2t(uint32_t* r, uint32_t addr) {
    asm volatile("ldmatrix.sync.aligned.m8n8.x2.trans.shared.b16 {%0,%1}, [%2];"
        : "=r"(r[0]), "=r"(r[1]) : "r"(addr));
}
__device__ __forceinline__ void mma_bf16(float* c, const uint32_t* a, const uint32_t* b) {
    asm volatile(
        "mma.sync.aligned.m16n8k16.row.col.f32.bf16.bf16.f32 "
        "{%0,%1,%2,%3}, {%4,%5,%6,%7}, {%8,%9}, {%0,%1,%2,%3};"
        : "+f"(c[0]), "+f"(c[1]), "+f"(c[2]), "+f"(c[3])
        : "r"(a[0]), "r"(a[1]), "r"(a[2]), "r"(a[3]), "r"(b[0]), "r"(b[1]));
}
__device__ __forceinline__ float gelu_exact(float v) {
    return 0.5f * v * (1.0f + erff(v * 0.7071067811865476f));
}
__device__ __forceinline__ uint32_t packbf(float a, float b) {
    __nv_bfloat162 t = __floats2bfloat162_rn(a, b);
    return *(uint32_t*)&t;
}

// ---------------------------------------------------------------------------
// Weight conversion fp32 -> bf16 (wqkv, wout, w2) + zero page
// ---------------------------------------------------------------------------
__global__ void wcvt(const float* __restrict__ wqkv, const float* __restrict__ wout,
                     const float* __restrict__ w2) {
    int i = blockIdx.x * 256 + threadIdx.x;
    if (i < 110592)       g_wqkv[i]          = __float2bfloat16(wqkv[i]);
    else if (i < 147456)  g_wout[i - 110592] = __float2bfloat16(wout[i - 110592]);
    else                  g_w2[i - 147456]   = __float2bfloat16(w2[i - 147456]);
    if (i < 16) g_zbuf[i] = __float2bfloat16(0.0f);
}

// Fold ln2 gamma into w1; compute per-n (S, T). One warp per n.
__global__ void prep1(const float* __restrict__ w1, const float* __restrict__ g2,
                      const float* __restrict__ b2) {
    int n = blockIdx.x * 8 + (threadIdx.x >> 5);
    int lane = threadIdx.x & 31;
    float S = 0.0f, T = 0.0f;
#pragma unroll
    for (int j = 0; j < 6; j++) {
        int k = lane + 32 * j;
        float w = w1[n * 192 + k];
        __nv_bfloat16 wb = __float2bfloat16(w * g2[k]);
        g_w1[n * 192 + k] = wb;
        S += __bfloat162float(wb);
        T += b2[k] * w;
    }
#pragma unroll
    for (int o = 16; o; o >>= 1) {
        S += __shfl_xor_sync(0xffffffffu, S, o);
        T += __shfl_xor_sync(0xffffffffu, T, o);
    }
    if (lane == 0) g_st1[n] = make_float2(S, T);
}

// Final LN2 stats: reduce the 6 proj-epilogue partial slots per token.
__global__ void finstats() {
    int i = blockIdx.x * 256 + threadIdx.x;
    float s = 0.0f, q = 0.0f;
#pragma unroll
    for (int k = 0; k < 6; k++) {
        float2 p = g_pbuf[k * NTOK + i];
        s += p.x; q += p.y;
    }
    float mean = s * (1.0f / 192.0f);
    float var  = q * (1.0f / 192.0f) - mean * mean;
    g_mstat[i] = make_float2(mean, rsqrtf(var + 1e-5f));
}

// ---------------------------------------------------------------------------
// LayerNorm 1: one warp per token, gather (shift+window partition), bf16 out.
// ---------------------------------------------------------------------------
__global__ void ln1_kernel(const float* __restrict__ x,
                           const float* __restrict__ gam,
                           const float* __restrict__ bet,
                           __nv_bfloat16* __restrict__ out) {
    int t    = blockIdx.x * 8 + (threadIdx.x >> 5);
    int lane = threadIdx.x & 31;
    const float* xr = x + (size_t)src_index(t) * DIM;

    float v[6];
#pragma unroll
    for (int i = 0; i < 6; i++) v[i] = xr[lane + 32 * i];

    float s = v[0] + v[1] + v[2] + v[3] + v[4] + v[5];
#pragma unroll
    for (int o = 16; o; o >>= 1) s += __shfl_xor_sync(0xffffffffu, s, o);
    float mean = s * (1.0f / 192.0f);

    float q = 0.0f;
#pragma unroll
    for (int i = 0; i < 6; i++) { float d = v[i] - mean; q += d * d; }
#pragma unroll
    for (int o = 16; o; o >>= 1) q += __shfl_xor_sync(0xffffffffu, q, o);
    float rstd = rsqrtf(q * (1.0f / 192.0f) + 1e-5f);

    __nv_bfloat16* orow = out + (size_t)t * DIM;
#pragma unroll
    for (int i = 0; i < 6; i++) {
        int c = lane + 32 * i;
        orow[c] = __float2bfloat16((v[i] - mean) * rstd * gam[c] + bet[c]);
    }
}

// ---------------------------------------------------------------------------
// Fused QKV-GEMM + window attention.
// CTA = (window pair p = blockIdx.x, head h = blockIdx.y). 256 thr, 8 warps.
// Phase 1: qkv[128 x 96] = a1[rows p*98 .. +127 (zero padded)] @ Whead^T + b
//          (cp.async 4-stage pipeline), result kept in SMEM only.
// Phase 2: per window (2 per CTA): S=QK^T, register softmax, O=PV (round-5
//          scheme, 4 warps x 16 rows per window), write ao.
// ---------------------------------------------------------------------------
#define FBK   16
#define FSTG  4
#define FAROW 24                          // pipeline smem row stride (bf16)
#define FASZ  (128 * FAROW * 2)           // 6144 B per A stage
#define FWSZ  (96 * FAROW * 2)            // 4608 B per B stage
#define QSTR  104                         // qkv smem row stride (bf16)
#define OFF_WS (FSTG * FASZ)              // 24576
#define OFF_QS (OFF_WS + FSTG * FWSZ)     // 43008
#define FUSED_SMEM (OFF_QS + 128 * QSTR * 2)  // 69632 B

__global__ __launch_bounds__(256, 2)
void attn_fused(const __nv_bfloat16* __restrict__ a1,
                const float* __restrict__ bqkv,
                __nv_bfloat16* __restrict__ ao) {
    extern __shared__ char smem[];
    const int tid  = threadIdx.x;
    const int warp = tid >> 5;
    const int lane = tid & 31;
    const int g    = lane >> 2;
    const int tin  = lane & 3;
    const int l15  = lane & 15;
    const int lhi  = lane >> 4;
    const int p    = blockIdx.x;          // window pair
    const int h    = blockIdx.y;          // head
    const int R0   = p * 98;

    // ---------------- Phase 1: QKV GEMM ----------------
    const int wm = (warp & 3) * 32;       // GEMM warp m offset
    const int wn = (warp >> 2) * 48;      // GEMM warp n offset

    const int arow = tid >> 1, achk = tid & 1;
    const bool areal = arow < 98;
    const __nv_bfloat16* Ag = areal ? (a1 + (size_t)(R0 + arow) * 192 + achk * 8)
                                    : (const __nv_bfloat16*)g_zbuf;
    const bool bld = tid < 192;
    int brow = (tid < 192) ? (tid >> 1) : 0;
    int bchk = tid & 1;
    const int bseg = brow >> 5;
    const __nv_bfloat16* Wg = g_wqkv + (size_t)(bseg * 192 + h * 32 + (brow & 31)) * 192 + bchk * 8;

    const uint32_t sb  = smem_u32(smem);
    const uint32_t asb = sb + (arow * FAROW + achk * 8) * 2;
    const uint32_t wsb = sb + OFF_WS + (brow * FAROW + bchk * 8) * 2;

#pragma unroll
    for (int s = 0; s < FSTG - 1; s++) {
        cp_async16(asb + s * FASZ, areal ? (Ag + s * FBK) : Ag);
        if (bld) cp_async16(wsb + s * FWSZ, Wg + s * FBK);
        CP_COMMIT();
    }

    float acc[2][6][4];
#pragma unroll
    for (int i = 0; i < 2; i++)
#pragma unroll
        for (int j = 0; j < 6; j++)
#pragma unroll
            for (int l = 0; l < 4; l++) acc[i][j][l] = 0.0f;

    const uint32_t albase = sb + ((wm + l15) * FAROW) * 2 + lhi * 16;

    for (int t = 0; t < 12; t++) {
        CP_WAIT(FSTG - 2);
        __syncthreads();
        const int tn = t + FSTG - 1;
        if (tn < 12) {
            const int s = tn % FSTG;
            cp_async16(asb + s * FASZ, areal ? (Ag + tn * FBK) : Ag);
            if (bld) cp_async16(wsb + s * FWSZ, Wg + tn * FBK);
        }
        CP_COMMIT();

        const int st = t % FSTG;
        uint32_t af[2][4];
        ldsm4(af[0], albase + st * FASZ);
        ldsm4(af[1], albase + st * FASZ + 16 * FAROW * 2);

        uint32_t bf[6][2];
        const __nv_bfloat16* wsr = (const __nv_bfloat16*)(smem + OFF_WS + st * FWSZ);
#pragma unroll
        for (int nt = 0; nt < 6; nt++) {
            const __nv_bfloat16* bp = wsr + (wn + nt * 8 + g) * FAROW + 2 * tin;
            bf[nt][0] = *(const uint32_t*)(bp);
            bf[nt][1] = *(const uint32_t*)(bp + 8);
        }
#pragma unroll
        for (int mt = 0; mt < 2; mt++)
#pragma unroll
            for (int nt = 0; nt < 6; nt++)
                mma_bf16(acc[mt][nt], af[mt], bf[nt]);
    }

    // epilogue: + bias, store q|k|v to SMEM (cols 0-31 q, 32-63 k, 64-95 v)
    __nv_bfloat16* qs = (__nv_bfloat16*)(smem + OFF_QS);
#pragma unroll
    for (int mt = 0; mt < 2; mt++) {
        const int r0 = wm + mt * 16 + g;
#pragma unroll
        for (int nt = 0; nt < 6; nt++) {
            const int nb  = wn + nt * 8;
            const int seg = nb >> 5;
            const int bcol = seg * 192 + h * 32 + (nb & 31) + 2 * tin;
            const float2 bv = *(const float2*)&bqkv[bcol];
            const int c = nb + 2 * tin;
            *(uint32_t*)&qs[r0 * QSTR + c]       = packbf(acc[mt][nt][0] + bv.x, acc[mt][nt][1] + bv.y);
            *(uint32_t*)&qs[(r0 + 8) * QSTR + c] = packbf(acc[mt][nt][2] + bv.x, acc[mt][nt][3] + bv.y);
        }
    }
    __syncthreads();

    // ---------------- Phase 2: attention ----------------
    const int wi = warp >> 2;             // window in pair
    const int mq = (warp & 3) * 16;       // row tile within window
    const int rb = wi * 49 + mq;
    const uint32_t qsu = sb + OFF_QS;

    float a7[7][4];
#pragma unroll
    for (int nt = 0; nt < 7; nt++)
#pragma unroll
        for (int c = 0; c < 4; c++) a7[nt][c] = 0.0f;

#pragma unroll
    for (int kc = 0; kc < 2; kc++) {
        uint32_t qa[4];
        ldsm4(qa, qsu + (uint32_t)(rb + l15) * (QSTR * 2) + kc * 32 + lhi * 16);
#pragma unroll
        for (int nt = 0; nt < 7; nt++) {
            uint32_t kb[2];
            ldsm2(kb, qsu + (uint32_t)(wi * 49 + nt * 8 + (lane & 7)) * (QSTR * 2)
                       + 64 + kc * 32 + ((lane >> 3) & 1) * 16);
            mma_bf16(a7[nt], qa, kb);
        }
    }

    const float scale = 0.17677669529663687f;   // 1/sqrt(32)
    float mx0 = -1e30f, mx1 = -1e30f;
#pragma unroll
    for (int nt = 0; nt < 7; nt++) {
        int c0 = nt * 8 + 2 * tin;
        float* a = a7[nt];
        a[0] = (c0     < 49) ? a[0] * scale : -1e30f;
        a[1] = (c0 + 1 < 49) ? a[1] * scale : -1e30f;
        a[2] = (c0     < 49) ? a[2] * scale : -1e30f;
        a[3] = (c0 + 1 < 49) ? a[3] * scale : -1e30f;
        mx0 = fmaxf(mx0, fmaxf(a[0], a[1]));
        mx1 = fmaxf(mx1, fmaxf(a[2], a[3]));
    }
    mx0 = fmaxf(mx0, __shfl_xor_sync(0xffffffffu, mx0, 1));
    mx0 = fmaxf(mx0, __shfl_xor_sync(0xffffffffu, mx0, 2));
    mx1 = fmaxf(mx1, __shfl_xor_sync(0xffffffffu, mx1, 1));
    mx1 = fmaxf(mx1, __shfl_xor_sync(0xffffffffu, mx1, 2));

    float s0 = 0.0f, s1 = 0.0f;
    uint32_t pk[8][2];
#pragma unroll
    for (int nt = 0; nt < 7; nt++) {
        float* a = a7[nt];
        a[0] = __expf(a[0] - mx0);
        a[1] = __expf(a[1] - mx0);
        a[2] = __expf(a[2] - mx1);
        a[3] = __expf(a[3] - mx1);
        s0 += a[0] + a[1];
        s1 += a[2] + a[3];
        pk[nt][0] = packbf(a[0], a[1]);
        pk[nt][1] = packbf(a[2], a[3]);
    }
    pk[7][0] = 0u; pk[7][1] = 0u;
    s0 += __shfl_xor_sync(0xffffffffu, s0, 1);
    s0 += __shfl_xor_sync(0xffffffffu, s0, 2);
    s1 += __shfl_xor_sync(0xffffffffu, s1, 1);
    s1 += __shfl_xor_sync(0xffffffffu, s1, 2);

    float pv[4][4];
#pragma unroll
    for (int nt = 0; nt < 4; nt++)
#pragma unroll
        for (int c = 0; c < 4; c++) pv[nt][c] = 0.0f;

#pragma unroll
    for (int kc = 0; kc < 4; kc++) {
        uint32_t pa[4] = { pk[2 * kc][0], pk[2 * kc][1], pk[2 * kc + 1][0], pk[2 * kc + 1][1] };
#pragma unroll
        for (int nt = 0; nt < 4; nt++) {
            uint32_t vb[2];
            ldsm2t(vb, qsu + (uint32_t)(wi * 49 + kc * 16 + l15) * (QSTR * 2)
                        + 128 + nt * 16);
            mma_bf16(pv[nt], pa, vb);
        }
    }

    const float inv0 = 1.0f / s0;
    const float inv1 = 1.0f / s1;
    const int rr0 = mq + g;
    if (rr0 < 49) {
        __nv_bfloat16* ob = ao + (size_t)(R0 + wi * 49 + rr0) * 192 + h * 32;
#pragma unroll
        for (int nt = 0; nt < 4; nt++)
            *(uint32_t*)&ob[nt * 8 + 2 * tin] = packbf(pv[nt][0] * inv0, pv[nt][1] * inv0);
    }
    if (rr0 + 8 < 49) {
        __nv_bfloat16* ob = ao + (size_t)(R0 + wi * 49 + rr0 + 8) * 192 + h * 32;
#pragma unroll
        for (int nt = 0; nt < 4; nt++)
            *(uint32_t*)&ob[nt * 8 + 2 * tin] = packbf(pv[nt][2] * inv1, pv[nt][3] * inv1);
    }
}

// ---------------------------------------------------------------------------
// bf16 GEMM (round-4 core). EPIs:
//   2: v += res[row]; fp32 store (fc2 -> out)
//   3: v += res[src(row)]; fp32 scatter store + bf16 copy + LN2 stat partials
//   4: LN2-affine (rstd*acc - mean*rstd*S + T + bias) then GELU, bf16 store
// ---------------------------------------------------------------------------
#define BM 128
#define BN 64
#define BK 16
#define STG 4
#define AROW 24

template <int EPI>
__global__ __launch_bounds__(256, 3)
void bgemm(const __nv_bfloat16* __restrict__ A, const __nv_bfloat16* __restrict__ W,
           const float* __restrict__ bias, void* __restrict__ outp,
           const float* __restrict__ res, int N, int K) {
    __shared__ __align__(16) __nv_bfloat16 As[STG][BM * AROW];
    __shared__ __align__(16) __nv_bfloat16 Ws[STG][BN * AROW];

    const int tid  = threadIdx.x;
    const int wid  = tid >> 5;
    const int lane = tid & 31;
    const int g    = lane >> 2;
    const int tin  = lane & 3;
    const int wm   = (wid & 3) * 32;
    const int wn   = (wid >> 2) * 32;
    const int row0 = blockIdx.y * BM;
    const int col0 = blockIdx.x * BN;

    const int arow = tid >> 1, achk = tid & 1;
    const int brow = (tid & 127) >> 1, bchk = tid & 1;
    const bool bld = tid < 128;

    const __nv_bfloat16* Ag = A + (size_t)(row0 + arow) * K + achk * 8;
    const __nv_bfloat16* Wg = W + (size_t)(col0 + brow) * K + bchk * 8;
    const uint32_t asb = smem_u32(As) + (arow * AROW + achk * 8) * 2;
    const uint32_t wsb = smem_u32(Ws) + (brow * AROW + bchk * 8) * 2;
    const uint32_t ASZ = BM * AROW * 2;
    const uint32_t WSZ = BN * AROW * 2;

    const int T = K / BK;
#pragma unroll
    for (int s = 0; s < STG - 1; s++) {
        cp_async16(asb + s * ASZ, Ag + s * BK);
        if (bld) cp_async16(wsb + s * WSZ, Wg + s * BK);
        CP_COMMIT();
    }

    float acc[2][4][4];
#pragma unroll
    for (int i = 0; i < 2; i++)
#pragma unroll
        for (int j = 0; j < 4; j++)
#pragma unroll
            for (int l = 0; l < 4; l++) acc[i][j][l] = 0.0f;

    const uint32_t albase = smem_u32(As) + ((wm + (lane & 15)) * AROW) * 2 + (lane >> 4) * 16;

    for (int t = 0; t < T; t++) {
        CP_WAIT(STG - 2);
        __syncthreads();
        const int tn = t + STG - 1;
        if (tn < T) {
            const int s = tn % STG;
            cp_async16(asb + s * ASZ, Ag + tn * BK);
            if (bld) cp_async16(wsb + s * WSZ, Wg + tn * BK);
        }
        CP_COMMIT();

        const int st = t % STG;
        uint32_t af[2][4];
        ldsm4(af[0], albase + st * ASZ);
        ldsm4(af[1], albase + st * ASZ + 16 * AROW * 2);

        uint32_t bf[4][2];
        const __nv_bfloat16* wsr = Ws[st];
#pragma unroll
        for (int nt = 0; nt < 4; nt++) {
            const __nv_bfloat16* bp = wsr + (wn + nt * 8 + g) * AROW + 2 * tin;
            bf[nt][0] = *(const uint32_t*)(bp);
            bf[nt][1] = *(const uint32_t*)(bp + 8);
        }
#pragma unroll
        for (int mt = 0; mt < 2; mt++)
#pragma unroll
            for (int nt = 0; nt < 4; nt++)
                mma_bf16(acc[mt][nt], af[mt], bf[nt]);
    }

    __nv_bfloat16* outb = (__nv_bfloat16*)outp;
    float*         outf = (float*)outp;

#pragma unroll
    for (int mt = 0; mt < 2; mt++) {
        const int r0 = row0 + wm + mt * 16 + g;
        const int r1 = r0 + 8;

        if (EPI == 3) {
            const int d0 = src_index(r0);
            const int d1 = src_index(r1);
            float s0 = 0.0f, q0 = 0.0f, s1 = 0.0f, q1 = 0.0f;
#pragma unroll
            for (int nt = 0; nt < 4; nt++) {
                const int col = col0 + wn + nt * 8 + 2 * tin;
                const float2 bv = *(const float2*)&bias[col];
                float2 v0, v1;
                v0.x = acc[mt][nt][0] + bv.x;
                v0.y = acc[mt][nt][1] + bv.y;
                v1.x = acc[mt][nt][2] + bv.x;
                v1.y = acc[mt][nt][3] + bv.y;
                float2 e0 = *(const float2*)&res[(size_t)d0 * 192 + col];
                float2 e1 = *(const float2*)&res[(size_t)d1 * 192 + col];
                v0.x += e0.x; v0.y += e0.y;
                v1.x += e1.x; v1.y += e1.y;
                *(float2*)&outf[(size_t)d0 * 192 + col] = v0;
                *(float2*)&outf[(size_t)d1 * 192 + col] = v1;
                *(uint32_t*)&g_x2b[(size_t)d0 * 192 + col] = packbf(v0.x, v0.y);
                *(uint32_t*)&g_x2b[(size_t)d1 * 192 + col] = packbf(v1.x, v1.y);
                s0 += v0.x + v0.y; q0 += v0.x * v0.x + v0.y * v0.y;
                s1 += v1.x + v1.y; q1 += v1.x * v1.x + v1.y * v1.y;
            }
            s0 += __shfl_xor_sync(0xffffffffu, s0, 1);
            s0 += __shfl_xor_sync(0xffffffffu, s0, 2);
            q0 += __shfl_xor_sync(0xffffffffu, q0, 1);
            q0 += __shfl_xor_sync(0xffffffffu, q0, 2);
            s1 += __shfl_xor_sync(0xffffffffu, s1, 1);
            s1 += __shfl_xor_sync(0xffffffffu, s1, 2);
            q1 += __shfl_xor_sync(0xffffffffu, q1, 1);
            q1 += __shfl_xor_sync(0xffffffffu, q1, 2);
            if (tin == 0) {
                const int slot = blockIdx.x * 2 + (wid >> 2);
                g_pbuf[slot * NTOK + d0] = make_float2(s0, q0);
                g_pbuf[slot * NTOK + d1] = make_float2(s1, q1);
            }
        } else if (EPI == 4) {
            const float2 mr0 = g_mstat[r0];
            const float2 mr1 = g_mstat[r1];
            const float a0 = mr0.y, b0 = mr0.x * mr0.y;
            const float a1 = mr1.y, b1c = mr1.x * mr1.y;
#pragma unroll
            for (int nt = 0; nt < 4; nt++) {
                const int col = col0 + wn + nt * 8 + 2 * tin;
                const float2 bv = *(const float2*)&bias[col];
                const float2 stA = g_st1[col];
                const float2 stB = g_st1[col + 1];
                float v00 = gelu_exact(a0 * acc[mt][nt][0] - b0 * stA.x + stA.y + bv.x);
                float v01 = gelu_exact(a0 * acc[mt][nt][1] - b0 * stB.x + stB.y + bv.y);
                float v10 = gelu_exact(a1 * acc[mt][nt][2] - b1c * stA.x + stA.y + bv.x);
                float v11 = gelu_exact(a1 * acc[mt][nt][3] - b1c * stB.x + stB.y + bv.y);
                *(uint32_t*)&outb[(size_t)r0 * N + col] = packbf(v00, v01);
                *(uint32_t*)&outb[(size_t)r1 * N + col] = packbf(v10, v11);
            }
        } else {  // EPI 2
#pragma unroll
            for (int nt = 0; nt < 4; nt++) {
                const int col = col0 + wn + nt * 8 + 2 * tin;
                const float2 bv = *(const float2*)&bias[col];
                float2 v0, v1;
                v0.x = acc[mt][nt][0] + bv.x;
                v0.y = acc[mt][nt][1] + bv.y;
                v1.x = acc[mt][nt][2] + bv.x;
                v1.y = acc[mt][nt][3] + bv.y;
                float2 e0 = *(const float2*)&res[(size_t)r0 * N + col];
                float2 e1 = *(const float2*)&res[(size_t)r1 * N + col];
                v0.x += e0.x; v0.y += e0.y;
                v1.x += e1.x; v1.y += e1.y;
                *(float2*)&outf[(size_t)r0 * N + col] = v0;
                *(float2*)&outf[(size_t)r1 * N + col] = v1;
            }
        }
    }
}

// ---------------------------------------------------------------------------
// Launcher
// ---------------------------------------------------------------------------
extern "C" void kernel_launch(void* const* d_in, const int* in_sizes, int n_in,
                              void* d_out, int out_size) {
    const float* x     = (const float*)d_in[0];
    const float* ln1_g = (const float*)d_in[1];
    const float* ln1_b = (const float*)d_in[2];
    const float* ln2_g = (const float*)d_in[3];
    const float* ln2_b = (const float*)d_in[4];
    const float* w_qkv = (const float*)d_in[5];
    const float* b_qkv = (const float*)d_in[6];
    const float* w_out = (const float*)d_in[7];
    const float* b_out = (const float*)d_in[8];
    const float* w1    = (const float*)d_in[9];
    const float* b1    = (const float*)d_in[10];
    const float* w2    = (const float*)d_in[11];
    const float* b2    = (const float*)d_in[12];
    float* out = (float*)d_out;

    __nv_bfloat16 *a1, *aob, *x2b, *hid, *wo, *ww1, *ww2;
    float* x2;
    cudaGetSymbolAddress((void**)&a1,  g_a1);
    cudaGetSymbolAddress((void**)&aob, g_ao);
    cudaGetSymbolAddress((void**)&x2,  g_x2);
    cudaGetSymbolAddress((void**)&x2b, g_x2b);
    cudaGetSymbolAddress((void**)&hid, g_hid);
    cudaGetSymbolAddress((void**)&wo,  g_wout);
    cudaGetSymbolAddress((void**)&ww1, g_w1);
    cudaGetSymbolAddress((void**)&ww2, g_w2);

    cudaFuncSetAttribute(attn_fused, cudaFuncAttributeMaxDynamicSharedMemorySize, FUSED_SMEM);

    // 0) weight prep
    wcvt<<<864, 256>>>(w_qkv, w_out, w2);
    prep1<<<48, 256>>>(w1, ln2_g, ln2_b);
    // 1) LN1 + shift + window partition -> a1 (bf16, window order)
    ln1_kernel<<<NTOK / 8, 256>>>(x, ln1_g, ln1_b, a1);
    // 2) fused QKV GEMM + attention -> ao (qkv stays in SMEM)
    attn_fused<<<dim3(1024, 6), 256, FUSED_SMEM>>>(a1, b_qkv, aob);
    // 3) proj + residual + scatter -> x2 fp32 + x2b bf16 + LN2 stat partials
    bgemm<3><<<dim3(3, NTOK / BM), 256>>>(aob, wo, b_out, x2, x, 192, 192);
    // 4) finalize LN2 stats
    finstats<<<NTOK / 256, 256>>>();
    // 5) fc1 (LN2 folded) + GELU -> hid
    bgemm<4><<<dim3(6, NTOK / BM), 256>>>(x2b, ww1, b1, hid, nullptr, 384, 192);
    // 6) fc2 + residual -> out
    bgemm<2><<<dim3(3, NTOK / BM), 256>>>(hid, ww2, b2, out, x2, 192, 384);
}

// round 7
// speedup vs baseline: 4.2708x; 1.0324x over previous
#include <cuda_runtime.h>
#include <cuda_bf16.h>
#include <math.h>
#include <stdint.h>

// ---------------------------------------------------------------------------
// Swin block: B=32, H=W=56, D=192, HEADS=6, DH=32, WS=7, SHIFT=3, no pad,
// no attention mask (per reference).
// R7: ldmatrix.x4 everywhere (B-frags, K-frags, V-frags) to cut the
// shared-pipe instruction count in the L1-bound fused kernel.
// ---------------------------------------------------------------------------

#define NHW   3136
#define NTOK  100352
#define DIM   192
#define NWIN  2048

__device__ __nv_bfloat16 g_a1 [(size_t)NTOK * DIM];   // LN1 out (window order)
__device__ __nv_bfloat16 g_ao [(size_t)NTOK * DIM];   // attn out (window order)
__device__ float         g_x2 [(size_t)NTOK * DIM];   // x2 fp32 (plain order)
__device__ __nv_bfloat16 g_x2b[(size_t)NTOK * DIM];   // x2 bf16 (plain order)
__device__ __nv_bfloat16 g_hid[(size_t)NTOK * 384];   // fc1 GELU out
__device__ __nv_bfloat16 g_wqkv[576 * 192];
__device__ __nv_bfloat16 g_wout[192 * 192];
__device__ __nv_bfloat16 g_w1  [384 * 192];           // gamma2-folded
__device__ __nv_bfloat16 g_w2  [192 * 384];
__device__ float2        g_st1 [384];                 // (S_n, T_n) for fc1 affine
__device__ float2        g_pbuf[6 * NTOK];            // per-slot (sum, sumsq)
__device__ float2        g_mstat[NTOK];               // (mean, rstd) of x2
__device__ __align__(16) __nv_bfloat16 g_zbuf[16];    // zero page for A padding

__device__ __forceinline__ int src_index(int r) {
    int w = r / 49, p = r % 49;
    int b  = w >> 6;
    int wy = (w & 63) >> 3;
    int wx = w & 7;
    int py = p / 7, px = p % 7;
    int h2 = wy * 7 + py;
    int w2 = wx * 7 + px;
    int hs = h2 + 3; if (hs >= 56) hs -= 56;
    int ws = w2 + 3; if (ws >= 56) ws -= 56;
    return b * NHW + hs * 56 + ws;
}

// ---------------------------------------------------------------------------
// PTX helpers (sm_80+; safe on plain sm_100 ptxas target)
// ---------------------------------------------------------------------------
__device__ __forceinline__ uint32_t smem_u32(const void* p) {
    uint32_t a;
    asm("{ .reg .u64 t; cvta.to.shared.u64 t, %1; cvt.u32.u64 %0, t; }" : "=r"(a) : "l"(p));
    return a;
}
__device__ __forceinline__ void cp_async16(uint32_t dst, const void* src) {
    asm volatile("cp.async.ca.shared.global [%0], [%1], 16;" :: "r"(dst), "l"(src));
}
#define CP_COMMIT()  asm volatile("cp.async.commit_group;" ::: "memory")
#define CP_WAIT(n)   asm volatile("cp.async.wait_group %0;" :: "n"(n) : "memory")

__device__ __forceinline__ void ldsm4(uint32_t* r, uint32_t addr) {
    asm volatile("ldmatrix.sync.aligned.m8n8.x4.shared.b16 {%0,%1,%2,%3}, [%4];"
        : "=r"(r[0]), "=r"(r[1]), "=r"(r[2]), "=r"(r[3]) : "r"(addr));
}
__device__ __forceinline__ void ldsm2(uint32_t* r, uint32_t addr) {
    asm volatile("ldmatrix.sync.aligned.m8n8.x2.shared.b16 {%0,%1}, [%2];"
        : "=r"(r[0]), "=r"(r[1]) : "r"(addr));
}
__device__ __forceinline__ void ldsm4t(uint32_t* r, uint32_t addr) {
    asm volatile("ldmatrix.sync.aligned.m8n8.x4.trans.shared.b16 {%0,%1,%2,%3}, [%4];"
        : "=r"(r[0]), "=r"(r[1]), "=r"(r[2]), "=r"(r[3]) : "r"(addr));
}
__device__ __forceinline__ void mma_bf16(float* c, const uint32_t* a, const uint32_t* b) {
    asm volatile(
        "mma.sync.aligned.m16n8k16.row.col.f32.bf16.bf16.f32 "
        "{%0,%1,%2,%3}, {%4,%5,%6,%7}, {%8,%9}, {%0,%1,%2,%3};"
        : "+f"(c[0]), "+f"(c[1]), "+f"(c[2]), "+f"(c[3])
        : "r"(a[0]), "r"(a[1]), "r"(a[2]), "r"(a[3]), "r"(b[0]), "r"(b[1]));
}
__device__ __forceinline__ float gelu_exact(float v) {
    return 0.5f * v * (1.0f + erff(v * 0.7071067811865476f));
}
__device__ __forceinline__ uint32_t packbf(float a, float b) {
    __nv_bfloat162 t = __floats2bfloat162_rn(a, b);
    return *(uint32_t*)&t;
}

// ---------------------------------------------------------------------------
// Weight conversion fp32 -> bf16 (wqkv, wout, w2) + zero page
// ---------------------------------------------------------------------------
__global__ void wcvt(const float* __restrict__ wqkv, const float* __restrict__ wout,
                     const float* __restrict__ w2) {
    int i = blockIdx.x * 256 + threadIdx.x;
    if (i < 110592)       g_wqkv[i]          = __float2bfloat16(wqkv[i]);
    else if (i < 147456)  g_wout[i - 110592] = __float2bfloat16(wout[i - 110592]);
    else                  g_w2[i - 147456]   = __float2bfloat16(w2[i - 147456]);
    if (i < 16) g_zbuf[i] = __float2bfloat16(0.0f);
}

// Fold ln2 gamma into w1; compute per-n (S, T). One warp per n.
__global__ void prep1(const float* __restrict__ w1, const float* __restrict__ g2,
                      const float* __restrict__ b2) {
    int n = blockIdx.x * 8 + (threadIdx.x >> 5);
    int lane = threadIdx.x & 31;
    float S = 0.0f, T = 0.0f;
#pragma unroll
    for (int j = 0; j < 6; j++) {
        int k = lane + 32 * j;
        float w = w1[n * 192 + k];
        __nv_bfloat16 wb = __float2bfloat16(w * g2[k]);
        g_w1[n * 192 + k] = wb;
        S += __bfloat162float(wb);
        T += b2[k] * w;
    }
#pragma unroll
    for (int o = 16; o; o >>= 1) {
        S += __shfl_xor_sync(0xffffffffu, S, o);
        T += __shfl_xor_sync(0xffffffffu, T, o);
    }
    if (lane == 0) g_st1[n] = make_float2(S, T);
}

// Final LN2 stats: reduce the 6 proj-epilogue partial slots per token.
__global__ void finstats() {
    int i = blockIdx.x * 256 + threadIdx.x;
    float s = 0.0f, q = 0.0f;
#pragma unroll
    for (int k = 0; k < 6; k++) {
        float2 p = g_pbuf[k * NTOK + i];
        s += p.x; q += p.y;
    }
    float mean = s * (1.0f / 192.0f);
    float var  = q * (1.0f / 192.0f) - mean * mean;
    g_mstat[i] = make_float2(mean, rsqrtf(var + 1e-5f));
}

// ---------------------------------------------------------------------------
// LayerNorm 1: one warp per token, gather (shift+window partition), bf16 out.
// ---------------------------------------------------------------------------
__global__ void ln1_kernel(const float* __restrict__ x,
                           const float* __restrict__ gam,
                           const float* __restrict__ bet,
                           __nv_bfloat16* __restrict__ out) {
    int t    = blockIdx.x * 8 + (threadIdx.x >> 5);
    int lane = threadIdx.x & 31;
    const float* xr = x + (size_t)src_index(t) * DIM;

    float v[6];
#pragma unroll
    for (int i = 0; i < 6; i++) v[i] = xr[lane + 32 * i];

    float s = v[0] + v[1] + v[2] + v[3] + v[4] + v[5];
#pragma unroll
    for (int o = 16; o; o >>= 1) s += __shfl_xor_sync(0xffffffffu, s, o);
    float mean = s * (1.0f / 192.0f);

    float q = 0.0f;
#pragma unroll
    for (int i = 0; i < 6; i++) { float d = v[i] - mean; q += d * d; }
#pragma unroll
    for (int o = 16; o; o >>= 1) q += __shfl_xor_sync(0xffffffffu, q, o);
    float rstd = rsqrtf(q * (1.0f / 192.0f) + 1e-5f);

    __nv_bfloat16* orow = out + (size_t)t * DIM;
#pragma unroll
    for (int i = 0; i < 6; i++) {
        int c = lane + 32 * i;
        orow[c] = __float2bfloat16((v[i] - mean) * rstd * gam[c] + bet[c]);
    }
}

// ---------------------------------------------------------------------------
// Fused QKV-GEMM + window attention. (round-6 structure, ldmatrix.x4 frags)
// ---------------------------------------------------------------------------
#define FBK   16
#define FSTG  4
#define FAROW 24                          // pipeline smem row stride (bf16)
#define FASZ  (128 * FAROW * 2)           // 6144 B per A stage
#define FWSZ  (96 * FAROW * 2)            // 4608 B per B stage
#define QSTR  104                         // qkv smem row stride (bf16)
#define OFF_WS (FSTG * FASZ)              // 24576
#define OFF_QS (OFF_WS + FSTG * FWSZ)     // 43008
#define FUSED_SMEM (OFF_QS + 128 * QSTR * 2)  // 69632 B

__global__ __launch_bounds__(256, 2)
void attn_fused(const __nv_bfloat16* __restrict__ a1,
                const float* __restrict__ bqkv,
                __nv_bfloat16* __restrict__ ao) {
    extern __shared__ char smem[];
    const int tid  = threadIdx.x;
    const int warp = tid >> 5;
    const int lane = tid & 31;
    const int g    = lane >> 2;
    const int tin  = lane & 3;
    const int l15  = lane & 15;
    const int lhi  = lane >> 4;
    const int p    = blockIdx.x;          // window pair
    const int h    = blockIdx.y;          // head
    const int R0   = p * 98;

    // ---------------- Phase 1: QKV GEMM ----------------
    const int wm = (warp & 3) * 32;
    const int wn = (warp >> 2) * 48;

    const int arow = tid >> 1, achk = tid & 1;
    const bool areal = arow < 98;
    const __nv_bfloat16* Ag = areal ? (a1 + (size_t)(R0 + arow) * 192 + achk * 8)
                                    : (const __nv_bfloat16*)g_zbuf;
    const bool bld = tid < 192;
    int brow = (tid < 192) ? (tid >> 1) : 0;
    int bchk = tid & 1;
    const int bseg = brow >> 5;
    const __nv_bfloat16* Wg = g_wqkv + (size_t)(bseg * 192 + h * 32 + (brow & 31)) * 192 + bchk * 8;

    const uint32_t sb  = smem_u32(smem);
    const uint32_t asb = sb + (arow * FAROW + achk * 8) * 2;
    const uint32_t wsb = sb + OFF_WS + (brow * FAROW + bchk * 8) * 2;

#pragma unroll
    for (int s = 0; s < FSTG - 1; s++) {
        cp_async16(asb + s * FASZ, areal ? (Ag + s * FBK) : Ag);
        if (bld) cp_async16(wsb + s * FWSZ, Wg + s * FBK);
        CP_COMMIT();
    }

    float acc[2][6][4];
#pragma unroll
    for (int i = 0; i < 2; i++)
#pragma unroll
        for (int j = 0; j < 6; j++)
#pragma unroll
            for (int l = 0; l < 4; l++) acc[i][j][l] = 0.0f;

    const uint32_t albase = sb + ((wm + l15) * FAROW) * 2 + lhi * 16;
    // B-frag ldsm4 lane address: row = wn + pair*16 + ((lane>>4)&1)*8 + (lane&7),
    // k 16B-half = (lane>>3)&1
    const uint32_t wbbase = sb + OFF_WS
                          + (uint32_t)(wn + ((lane >> 4) & 1) * 8 + (lane & 7)) * (FAROW * 2)
                          + ((lane >> 3) & 1) * 16;

    for (int t = 0; t < 12; t++) {
        CP_WAIT(FSTG - 2);
        __syncthreads();
        const int tn = t + FSTG - 1;
        if (tn < 12) {
            const int s = tn % FSTG;
            cp_async16(asb + s * FASZ, areal ? (Ag + tn * FBK) : Ag);
            if (bld) cp_async16(wsb + s * FWSZ, Wg + tn * FBK);
        }
        CP_COMMIT();

        const int st = t % FSTG;
        uint32_t af[2][4];
        ldsm4(af[0], albase + st * FASZ);
        ldsm4(af[1], albase + st * FASZ + 16 * FAROW * 2);

        uint32_t bq[3][4];
#pragma unroll
        for (int pr = 0; pr < 3; pr++)
            ldsm4(bq[pr], wbbase + st * FWSZ + pr * 16 * (FAROW * 2));

#pragma unroll
        for (int mt = 0; mt < 2; mt++)
#pragma unroll
            for (int pr = 0; pr < 3; pr++) {
                mma_bf16(acc[mt][2 * pr + 0], af[mt], &bq[pr][0]);
                mma_bf16(acc[mt][2 * pr + 1], af[mt], &bq[pr][2]);
            }
    }

    // epilogue: + bias, store q|k|v to SMEM (cols 0-31 q, 32-63 k, 64-95 v)
    __nv_bfloat16* qs = (__nv_bfloat16*)(smem + OFF_QS);
#pragma unroll
    for (int mt = 0; mt < 2; mt++) {
        const int r0 = wm + mt * 16 + g;
#pragma unroll
        for (int nt = 0; nt < 6; nt++) {
            const int nb  = wn + nt * 8;
            const int seg = nb >> 5;
            const int bcol = seg * 192 + h * 32 + (nb & 31) + 2 * tin;
            const float2 bv = *(const float2*)&bqkv[bcol];
            const int c = nb + 2 * tin;
            *(uint32_t*)&qs[r0 * QSTR + c]       = packbf(acc[mt][nt][0] + bv.x, acc[mt][nt][1] + bv.y);
            *(uint32_t*)&qs[(r0 + 8) * QSTR + c] = packbf(acc[mt][nt][2] + bv.x, acc[mt][nt][3] + bv.y);
        }
    }
    __syncthreads();

    // ---------------- Phase 2: attention ----------------
    const int wi = warp >> 2;             // window in pair
    const int mq = (warp & 3) * 16;       // row tile within window
    const int rb = wi * 49 + mq;
    const uint32_t qsu = sb + OFF_QS;

    float a7[7][4];
#pragma unroll
    for (int nt = 0; nt < 7; nt++)
#pragma unroll
        for (int c = 0; c < 4; c++) a7[nt][c] = 0.0f;

    // K-frag ldsm4 base (pairs of nt): row = wi*49 + pr*16 + ((lane>>4)&1)*8 + (lane&7)
    const uint32_t kbase = qsu
        + (uint32_t)(wi * 49 + ((lane >> 4) & 1) * 8 + (lane & 7)) * (QSTR * 2)
        + 64 + ((lane >> 3) & 1) * 16;

#pragma unroll
    for (int kc = 0; kc < 2; kc++) {
        uint32_t qa[4];
        ldsm4(qa, qsu + (uint32_t)(rb + l15) * (QSTR * 2) + kc * 32 + lhi * 16);
        uint32_t kq[3][4];
#pragma unroll
        for (int pr = 0; pr < 3; pr++)
            ldsm4(kq[pr], kbase + kc * 32 + pr * 16 * (QSTR * 2));
        uint32_t k6[2];
        ldsm2(k6, qsu + (uint32_t)(wi * 49 + 48 + (lane & 7)) * (QSTR * 2)
                   + 64 + kc * 32 + ((lane >> 3) & 1) * 16);
#pragma unroll
        for (int pr = 0; pr < 3; pr++) {
            mma_bf16(a7[2 * pr + 0], qa, &kq[pr][0]);
            mma_bf16(a7[2 * pr + 1], qa, &kq[pr][2]);
        }
        mma_bf16(a7[6], qa, k6);
    }

    const float scale = 0.17677669529663687f;   // 1/sqrt(32)
    float mx0 = -1e30f, mx1 = -1e30f;
#pragma unroll
    for (int nt = 0; nt < 7; nt++) {
        int c0 = nt * 8 + 2 * tin;
        float* a = a7[nt];
        a[0] = (c0     < 49) ? a[0] * scale : -1e30f;
        a[1] = (c0 + 1 < 49) ? a[1] * scale : -1e30f;
        a[2] = (c0     < 49) ? a[2] * scale : -1e30f;
        a[3] = (c0 + 1 < 49) ? a[3] * scale : -1e30f;
        mx0 = fmaxf(mx0, fmaxf(a[0], a[1]));
        mx1 = fmaxf(mx1, fmaxf(a[2], a[3]));
    }
    mx0 = fmaxf(mx0, __shfl_xor_sync(0xffffffffu, mx0, 1));
    mx0 = fmaxf(mx0, __shfl_xor_sync(0xffffffffu, mx0, 2));
    mx1 = fmaxf(mx1, __shfl_xor_sync(0xffffffffu, mx1, 1));
    mx1 = fmaxf(mx1, __shfl_xor_sync(0xffffffffu, mx1, 2));

    float s0 = 0.0f, s1 = 0.0f;
    uint32_t pk[8][2];
#pragma unroll
    for (int nt = 0; nt < 7; nt++) {
        float* a = a7[nt];
        a[0] = __expf(a[0] - mx0);
        a[1] = __expf(a[1] - mx0);
        a[2] = __expf(a[2] - mx1);
        a[3] = __expf(a[3] - mx1);
        s0 += a[0] + a[1];
        s1 += a[2] + a[3];
        pk[nt][0] = packbf(a[0], a[1]);
        pk[nt][1] = packbf(a[2], a[3]);
    }
    pk[7][0] = 0u; pk[7][1] = 0u;
    s0 += __shfl_xor_sync(0xffffffffu, s0, 1);
    s0 += __shfl_xor_sync(0xffffffffu, s0, 2);
    s1 += __shfl_xor_sync(0xffffffffu, s1, 1);
    s1 += __shfl_xor_sync(0xffffffffu, s1, 2);

    float pv[4][4];
#pragma unroll
    for (int nt = 0; nt < 4; nt++)
#pragma unroll
        for (int c = 0; c < 4; c++) pv[nt][c] = 0.0f;

    // V-frag ldsm4t base (pairs of nt): rows = window rows, col = 128 + (pr*2 + lane>>4)*16
    const uint32_t vbase = qsu + (uint32_t)(wi * 49 + l15) * (QSTR * 2) + 128 + lhi * 16;

#pragma unroll
    for (int kc = 0; kc < 4; kc++) {
        uint32_t pa[4] = { pk[2 * kc][0], pk[2 * kc][1], pk[2 * kc + 1][0], pk[2 * kc + 1][1] };
        uint32_t vq[2][4];
#pragma unroll
        for (int pr = 0; pr < 2; pr++)
            ldsm4t(vq[pr], vbase + kc * 16 * (QSTR * 2) + pr * 32);
#pragma unroll
        for (int pr = 0; pr < 2; pr++) {
            mma_bf16(pv[2 * pr + 0], pa, &vq[pr][0]);
            mma_bf16(pv[2 * pr + 1], pa, &vq[pr][2]);
        }
    }

    const float inv0 = 1.0f / s0;
    const float inv1 = 1.0f / s1;
    const int rr0 = mq + g;
    if (rr0 < 49) {
        __nv_bfloat16* ob = ao + (size_t)(R0 + wi * 49 + rr0) * 192 + h * 32;
#pragma unroll
        for (int nt = 0; nt < 4; nt++)
            *(uint32_t*)&ob[nt * 8 + 2 * tin] = packbf(pv[nt][0] * inv0, pv[nt][1] * inv0);
    }
    if (rr0 + 8 < 49) {
        __nv_bfloat16* ob = ao + (size_t)(R0 + wi * 49 + rr0 + 8) * 192 + h * 32;
#pragma unroll
        for (int nt = 0; nt < 4; nt++)
            *(uint32_t*)&ob[nt * 8 + 2 * tin] = packbf(pv[nt][2] * inv1, pv[nt][3] * inv1);
    }
}

// ---------------------------------------------------------------------------
// bf16 GEMM (round-6 EPIs, ldmatrix.x4 B-frags)
// ---------------------------------------------------------------------------
#define BM 128
#define BN 64
#define BK 16
#define STG 4
#define AROW 24

template <int EPI>
__global__ __launch_bounds__(256, 3)
void bgemm(const __nv_bfloat16* __restrict__ A, const __nv_bfloat16* __restrict__ W,
           const float* __restrict__ bias, void* __restrict__ outp,
           const float* __restrict__ res, int N, int K) {
    __shared__ __align__(16) __nv_bfloat16 As[STG][BM * AROW];
    __shared__ __align__(16) __nv_bfloat16 Ws[STG][BN * AROW];

    const int tid  = threadIdx.x;
    const int wid  = tid >> 5;
    const int lane = tid & 31;
    const int g    = lane >> 2;
    const int tin  = lane & 3;
    const int wm   = (wid & 3) * 32;
    const int wn   = (wid >> 2) * 32;
    const int row0 = blockIdx.y * BM;
    const int col0 = blockIdx.x * BN;

    const int arow = tid >> 1, achk = tid & 1;
    const int brow = (tid & 127) >> 1, bchk = tid & 1;
    const bool bld = tid < 128;

    const __nv_bfloat16* Ag = A + (size_t)(row0 + arow) * K + achk * 8;
    const __nv_bfloat16* Wg = W + (size_t)(col0 + brow) * K + bchk * 8;
    const uint32_t asb = smem_u32(As) + (arow * AROW + achk * 8) * 2;
    const uint32_t wsb = smem_u32(Ws) + (brow * AROW + bchk * 8) * 2;
    const uint32_t ASZ = BM * AROW * 2;
    const uint32_t WSZ = BN * AROW * 2;

    const int T = K / BK;
#pragma unroll
    for (int s = 0; s < STG - 1; s++) {
        cp_async16(asb + s * ASZ, Ag + s * BK);
        if (bld) cp_async16(wsb + s * WSZ, Wg + s * BK);
        CP_COMMIT();
    }

    float acc[2][4][4];
#pragma unroll
    for (int i = 0; i < 2; i++)
#pragma unroll
        for (int j = 0; j < 4; j++)
#pragma unroll
            for (int l = 0; l < 4; l++) acc[i][j][l] = 0.0f;

    const uint32_t albase = smem_u32(As) + ((wm + (lane & 15)) * AROW) * 2 + (lane >> 4) * 16;
    const uint32_t wbbase = smem_u32(Ws)
                          + (uint32_t)(wn + ((lane >> 4) & 1) * 8 + (lane & 7)) * (AROW * 2)
                          + ((lane >> 3) & 1) * 16;

    for (int t = 0; t < T; t++) {
        CP_WAIT(STG - 2);
        __syncthreads();
        const int tn = t + STG - 1;
        if (tn < T) {
            const int s = tn % STG;
            cp_async16(asb + s * ASZ, Ag + tn * BK);
            if (bld) cp_async16(wsb + s * WSZ, Wg + tn * BK);
        }
        CP_COMMIT();

        const int st = t % STG;
        uint32_t af[2][4];
        ldsm4(af[0], albase + st * ASZ);
        ldsm4(af[1], albase + st * ASZ + 16 * AROW * 2);

        uint32_t bq[2][4];
        ldsm4(bq[0], wbbase + st * WSZ);
        ldsm4(bq[1], wbbase + st * WSZ + 16 * (AROW * 2));

#pragma unroll
        for (int mt = 0; mt < 2; mt++) {
            mma_bf16(acc[mt][0], af[mt], &bq[0][0]);
            mma_bf16(acc[mt][1], af[mt], &bq[0][2]);
            mma_bf16(acc[mt][2], af[mt], &bq[1][0]);
            mma_bf16(acc[mt][3], af[mt], &bq[1][2]);
        }
    }

    __nv_bfloat16* outb = (__nv_bfloat16*)outp;
    float*         outf = (float*)outp;

#pragma unroll
    for (int mt = 0; mt < 2; mt++) {
        const int r0 = row0 + wm + mt * 16 + g;
        const int r1 = r0 + 8;

        if (EPI == 3) {
            const int d0 = src_index(r0);
            const int d1 = src_index(r1);
            float s0 = 0.0f, q0 = 0.0f, s1 = 0.0f, q1 = 0.0f;
#pragma unroll
            for (int nt = 0; nt < 4; nt++) {
                const int col = col0 + wn + nt * 8 + 2 * tin;
                const float2 bv = *(const float2*)&bias[col];
                float2 v0, v1;
                v0.x = acc[mt][nt][0] + bv.x;
                v0.y = acc[mt][nt][1] + bv.y;
                v1.x = acc[mt][nt][2] + bv.x;
                v1.y = acc[mt][nt][3] + bv.y;
                float2 e0 = *(const float2*)&res[(size_t)d0 * 192 + col];
                float2 e1 = *(const float2*)&res[(size_t)d1 * 192 + col];
                v0.x += e0.x; v0.y += e0.y;
                v1.x += e1.x; v1.y += e1.y;
                *(float2*)&outf[(size_t)d0 * 192 + col] = v0;
                *(float2*)&outf[(size_t)d1 * 192 + col] = v1;
                *(uint32_t*)&g_x2b[(size_t)d0 * 192 + col] = packbf(v0.x, v0.y);
                *(uint32_t*)&g_x2b[(size_t)d1 * 192 + col] = packbf(v1.x, v1.y);
                s0 += v0.x + v0.y; q0 += v0.x * v0.x + v0.y * v0.y;
                s1 += v1.x + v1.y; q1 += v1.x * v1.x + v1.y * v1.y;
            }
            s0 += __shfl_xor_sync(0xffffffffu, s0, 1);
            s0 += __shfl_xor_sync(0xffffffffu, s0, 2);
            q0 += __shfl_xor_sync(0xffffffffu, q0, 1);
            q0 += __shfl_xor_sync(0xffffffffu, q0, 2);
            s1 += __shfl_xor_sync(0xffffffffu, s1, 1);
            s1 += __shfl_xor_sync(0xffffffffu, s1, 2);
            q1 += __shfl_xor_sync(0xffffffffu, q1, 1);
            q1 += __shfl_xor_sync(0xffffffffu, q1, 2);
            if (tin == 0) {
                const int slot = blockIdx.x * 2 + (wid >> 2);
                g_pbuf[slot * NTOK + d0] = make_float2(s0, q0);
                g_pbuf[slot * NTOK + d1] = make_float2(s1, q1);
            }
        } else if (EPI == 4) {
            const float2 mr0 = g_mstat[r0];
            const float2 mr1 = g_mstat[r1];
            const float a0 = mr0.y, b0 = mr0.x * mr0.y;
            const float a1 = mr1.y, b1c = mr1.x * mr1.y;
#pragma unroll
            for (int nt = 0; nt < 4; nt++) {
                const int col = col0 + wn + nt * 8 + 2 * tin;
                const float2 bv = *(const float2*)&bias[col];
                const float2 stA = g_st1[col];
                const float2 stB = g_st1[col + 1];
                float v00 = gelu_exact(a0 * acc[mt][nt][0] - b0 * stA.x + stA.y + bv.x);
                float v01 = gelu_exact(a0 * acc[mt][nt][1] - b0 * stB.x + stB.y + bv.y);
                float v10 = gelu_exact(a1 * acc[mt][nt][2] - b1c * stA.x + stA.y + bv.x);
                float v11 = gelu_exact(a1 * acc[mt][nt][3] - b1c * stB.x + stB.y + bv.y);
                *(uint32_t*)&outb[(size_t)r0 * N + col] = packbf(v00, v01);
                *(uint32_t*)&outb[(size_t)r1 * N + col] = packbf(v10, v11);
            }
        } else {  // EPI 2
#pragma unroll
            for (int nt = 0; nt < 4; nt++) {
                const int col = col0 + wn + nt * 8 + 2 * tin;
                const float2 bv = *(const float2*)&bias[col];
                float2 v0, v1;
                v0.x = acc[mt][nt][0] + bv.x;
                v0.y = acc[mt][nt][1] + bv.y;
                v1.x = acc[mt][nt][2] + bv.x;
                v1.y = acc[mt][nt][3] + bv.y;
                float2 e0 = *(const float2*)&res[(size_t)r0 * N + col];
                float2 e1 = *(const float2*)&res[(size_t)r1 * N + col];
                v0.x += e0.x; v0.y += e0.y;
                v1.x += e1.x; v1.y += e1.y;
                *(float2*)&outf[(size_t)r0 * N + col] = v0;
                *(float2*)&outf[(size_t)r1 * N + col] = v1;
            }
        }
    }
}

// ---------------------------------------------------------------------------
// Launcher
// ---------------------------------------------------------------------------
extern "C" void kernel_launch(void* const* d_in, const int* in_sizes, int n_in,
                              void* d_out, int out_size) {
    const float* x     = (const float*)d_in[0];
    const float* ln1_g = (const float*)d_in[1];
    const float* ln1_b = (const float*)d_in[2];
    const float* ln2_g = (const float*)d_in[3];
    const float* ln2_b = (const float*)d_in[4];
    const float* w_qkv = (const float*)d_in[5];
    const float* b_qkv = (const float*)d_in[6];
    const float* w_out = (const float*)d_in[7];
    const float* b_out = (const float*)d_in[8];
    const float* w1    = (const float*)d_in[9];
    const float* b1    = (const float*)d_in[10];
    const float* w2    = (const float*)d_in[11];
    const float* b2    = (const float*)d_in[12];
    float* out = (float*)d_out;

    __nv_bfloat16 *a1, *aob, *x2b, *hid, *wo, *ww1, *ww2;
    float* x2;
    cudaGetSymbolAddress((void**)&a1,  g_a1);
    cudaGetSymbolAddress((void**)&aob, g_ao);
    cudaGetSymbolAddress((void**)&x2,  g_x2);
    cudaGetSymbolAddress((void**)&x2b, g_x2b);
    cudaGetSymbolAddress((void**)&hid, g_hid);
    cudaGetSymbolAddress((void**)&wo,  g_wout);
    cudaGetSymbolAddress((void**)&ww1, g_w1);
    cudaGetSymbolAddress((void**)&ww2, g_w2);

    cudaFuncSetAttribute(attn_fused, cudaFuncAttributeMaxDynamicSharedMemorySize, FUSED_SMEM);

    // 0) weight prep
    wcvt<<<864, 256>>>(w_qkv, w_out, w2);
    prep1<<<48, 256>>>(w1, ln2_g, ln2_b);
    // 1) LN1 + shift + window partition -> a1 (bf16, window order)
    ln1_kernel<<<NTOK / 8, 256>>>(x, ln1_g, ln1_b, a1);
    // 2) fused QKV GEMM + attention -> ao (qkv stays in SMEM)
    attn_fused<<<dim3(1024, 6), 256, FUSED_SMEM>>>(a1, b_qkv, aob);
    // 3) proj + residual + scatter -> x2 fp32 + x2b bf16 + LN2 stat partials
    bgemm<3><<<dim3(3, NTOK / BM), 256>>>(aob, wo, b_out, x2, x, 192, 192);
    // 4) finalize LN2 stats
    finstats<<<NTOK / 256, 256>>>();
    // 5) fc1 (LN2 folded) + GELU -> hid
    bgemm<4><<<dim3(6, NTOK / BM), 256>>>(x2b, ww1, b1, hid, nullptr, 384, 192);
    // 6) fc2 + residual -> out
    bgemm<2><<<dim3(3, NTOK / BM), 256>>>(hid, ww2, b2, out, x2, 192, 384);
}